// round 15
// baseline (speedup 1.0000x reference)
#include <cuda_runtime.h>
#include <cuda_bf16.h>
#include <stdint.h>
#include <math.h>

#define BATCH 16384
#define HID   256
#define LATD  64
#define NSTEP 63

#define OUT_S_OFF  (BATCH*LATD)
#define OUT_Z_OFF  (2*BATCH*LATD)
#define ZSLICE     (BATCH*LATD)

// ---------------- scratch (static device arrays; no allocation) ----------------
__device__ __nv_bfloat16 g_xh[BATCH*HID], g_xl[BATCH*HID];
__device__ __nv_bfloat16 g_ah[BATCH*HID], g_al[BATCH*HID];
__device__ __nv_bfloat16 g_bh[BATCH*HID], g_bl[BATCH*HID];
__device__ __nv_bfloat16 g_gh[BATCH*HID], g_gl[BATCH*HID];
__device__ float g_hres[BATCH*HID];

// combined [Wd1|Wg1] weights: [64][512]
__device__ __nv_bfloat16 g_wdgh[64*512], g_wdgl[64*512];
__device__ float g_bdg[512], g_w0dg[512];

// weight scratch: elementwise hi/lo split, natural [K][N] layout
#define OFF_WIN   0
#define OFF_WB1   65536
#define OFF_WB2   (OFF_WB1 + 3*65536)
#define OFF_WFO   (OFF_WB2 + 3*65536)
#define OFF_WLAT  (OFF_WFO + 65536)
#define OFF_WINIT (OFF_WLAT + 32768)
#define OFF_WD2   (OFF_WINIT + 16384)
#define OFF_WD3   (OFF_WD2 + 65536)
#define OFF_WG2   (OFF_WD3 + 16384)
#define WT_TOTAL  (OFF_WG2 + 16384)

__device__ __nv_bfloat16 g_wh[WT_TOTAL];
__device__ __nv_bfloat16 g_wl[WT_TOTAL];

enum { ACT_NONE=0, ACT_SWISH=1, ACT_SOFTPLUS=2 };

__device__ __forceinline__ float f_swish(float v){
    return v * (1.0f / (1.0f + __expf(-v)));
}
__device__ __forceinline__ float f_softplus(float v){
    return fmaxf(v, 0.0f) + log1pf(__expf(-fabsf(v)));
}

__device__ __forceinline__ uint32_t smem_u32(const void* p){
    uint32_t a;
    asm("{ .reg .u64 t; cvta.to.shared.u64 t, %1; cvt.u32.u64 %0, t; }" : "=r"(a) : "l"(p));
    return a;
}
__device__ __forceinline__ void ldsm4(uint32_t (&r)[4], uint32_t addr){
    asm volatile("ldmatrix.sync.aligned.m8n8.x4.shared.b16 {%0,%1,%2,%3}, [%4];"
        : "=r"(r[0]),"=r"(r[1]),"=r"(r[2]),"=r"(r[3]) : "r"(addr));
}
__device__ __forceinline__ void ldsm4t(uint32_t (&r)[4], uint32_t addr){
    asm volatile("ldmatrix.sync.aligned.m8n8.x4.trans.shared.b16 {%0,%1,%2,%3}, [%4];"
        : "=r"(r[0]),"=r"(r[1]),"=r"(r[2]),"=r"(r[3]) : "r"(addr));
}
__device__ __forceinline__ void mma_bf16(float (&d)[4], const uint32_t (&a)[4],
                                         uint32_t b0, uint32_t b1){
    asm volatile(
        "mma.sync.aligned.m16n8k16.row.col.f32.bf16.bf16.f32 "
        "{%0,%1,%2,%3}, {%4,%5,%6,%7}, {%8,%9}, {%0,%1,%2,%3};"
        : "+f"(d[0]),"+f"(d[1]),"+f"(d[2]),"+f"(d[3])
        : "r"(a[0]),"r"(a[1]),"r"(a[2]),"r"(a[3]), "r"(b0),"r"(b1));
}
__device__ __forceinline__ void cpa16(uint32_t dst, const void* src){
    asm volatile("cp.async.cg.shared.global [%0], [%1], 16;" :: "r"(dst), "l"(src));
}
#define CP_COMMIT() asm volatile("cp.async.commit_group;" ::: "memory")
#define CP_WAIT(n)  asm volatile("cp.async.wait_group %0;" :: "n"(n) : "memory")

// ---------------------------------------------------------------------------
// Single-pass 3-product MMA block (Ah*Bh + Al*Bh + Ah*Bl).
// ---------------------------------------------------------------------------
template<int NP>
__device__ __forceinline__ void mma_block(
    float (&acc)[2][NP*2][4],
    uint32_t AHb, uint32_t ALb, uint32_t BHb, uint32_t BLb,
    int wm, int wnbase, int lid)
{
    #pragma unroll
    for (int kk = 0; kk < 4; kk++) {
        uint32_t a0h[4], a1h[4], a0l[4], a1l[4];
        {
            int row = wm*32 + (lid&7) + ((lid>>3)&1)*8;
            int gg  = kk*2 + (lid>>4);
            uint32_t off = (uint32_t)(row*128 + gg*16); off ^= (off>>3)&0x70;
            ldsm4(a0h, AHb + off);
            ldsm4(a0l, ALb + off);
            uint32_t off2 = (uint32_t)((row+16)*128 + gg*16); off2 ^= (off2>>3)&0x70;
            ldsm4(a1h, AHb + off2);
            ldsm4(a1l, ALb + off2);
        }
        const int krow = kk*16 + (lid&7) + ((lid>>3)&1)*8;
        #pragma unroll
        for (int np = 0; np < NP; np++) {
            int colb = wnbase + np*16;
            int sbt  = colb >> 6;
            int gg   = ((colb & 63) >> 3) + (lid>>4);
            uint32_t off = (uint32_t)(krow*128 + gg*16); off ^= (off>>3)&0x70;
            off += (uint32_t)sbt * 8192;
            uint32_t b[4], bl[4];
            ldsm4t(b,  BHb + off);
            ldsm4t(bl, BLb + off);
            mma_bf16(acc[0][np*2  ], a0h, b[0], b[1]);
            mma_bf16(acc[1][np*2  ], a1h, b[0], b[1]);
            mma_bf16(acc[0][np*2+1], a0h, b[2], b[3]);
            mma_bf16(acc[1][np*2+1], a1h, b[2], b[3]);
            mma_bf16(acc[0][np*2  ], a0l, b[0], b[1]);
            mma_bf16(acc[1][np*2  ], a1l, b[0], b[1]);
            mma_bf16(acc[0][np*2+1], a0l, b[2], b[3]);
            mma_bf16(acc[1][np*2+1], a1l, b[2], b[3]);
            mma_bf16(acc[0][np*2  ], a0h, bl[0], bl[1]);
            mma_bf16(acc[1][np*2  ], a1h, bl[0], bl[1]);
            mma_bf16(acc[0][np*2+1], a0h, bl[2], bl[3]);
            mma_bf16(acc[1][np*2+1], a1h, bl[2], bl[3]);
        }
    }
}

// ---------------------------------------------------------------------------
// (encoder) mma.sync bf16 split GEMM — unchanged.
// ---------------------------------------------------------------------------
template<int K, int NG, int ACT, bool RES, bool WBF, bool WF32>
__global__ void __launch_bounds__(256,2) mgemm(
    const __nv_bfloat16* __restrict__ Ah_g, const __nv_bfloat16* __restrict__ Al_g,
    const __nv_bfloat16* __restrict__ Bh_g, const __nv_bfloat16* __restrict__ Bl_g,
    const float* __restrict__ bias,
    const float* __restrict__ resp,
    float* __restrict__ outF,
    __nv_bfloat162* __restrict__ outBh, __nv_bfloat162* __restrict__ outBl)
{
    constexpr int BN  = (NG >= 128) ? 128 : 64;
    constexpr int WN  = BN / 2;
    constexpr int NP  = WN / 16;
    constexpr int NCH = K / 64;
    constexpr int BSZ = BN * 128;
    constexpr int AHo = 0, ALo = 16384, BHo = 32768, BLo = 32768 + BSZ;

    extern __shared__ char sm[];
    const int tid = threadIdx.x;
    const int lid = tid & 31, wid = tid >> 5;
    const int wm  = wid & 3;
    const int wn  = wid >> 2;
    const int m0  = blockIdx.x * 128;
    const int n0c = blockIdx.y * BN;
    const uint32_t sb = smem_u32(sm);

    float acc[2][NP*2][4];
    #pragma unroll
    for (int i=0;i<2;i++)
        #pragma unroll
        for (int j=0;j<NP*2;j++)
            #pragma unroll
            for (int q=0;q<4;q++) acc[i][j][q] = 0.0f;

    for (int c = 0; c < NCH; c++) {
        const int c64 = c * 64;
        if (c) __syncthreads();

        #pragma unroll
        for (int it = 0; it < 4; it++) {
            int g = tid + it*256;
            int row = g >> 3, gg = g & 7;
            uint32_t off = (uint32_t)(row*128 + gg*16);
            off ^= (off >> 3) & 0x70;
            size_t src = (size_t)(m0+row)*K + c64 + gg*8;
            *(uint4*)(sm + AHo + off) = *(const uint4*)(Ah_g + src);
            *(uint4*)(sm + ALo + off) = *(const uint4*)(Al_g + src);
        }
        #pragma unroll
        for (int it = 0; it < BN/32; it++) {
            int g = tid + it*256;
            int row, gg;
            if (BN == 128) { row = g >> 4; gg = g & 15; }
            else           { row = g >> 3; gg = g & 7;  }
            int s = gg >> 3, gin = gg & 7;
            uint32_t off = (uint32_t)(row*128 + gin*16);
            off ^= (off >> 3) & 0x70;
            off += (uint32_t)s * 8192;
            size_t src = (size_t)(c64+row)*NG + n0c + gg*8;
            *(uint4*)(sm + BHo + off) = *(const uint4*)(Bh_g + src);
            *(uint4*)(sm + BLo + off) = *(const uint4*)(Bl_g + src);
        }
        __syncthreads();

        mma_block<NP>(acc, sb+AHo, sb+ALo, sb+BHo, sb+BLo, wm, wn*WN, lid);
    }

    #pragma unroll
    for (int nt = 0; nt < NP*2; nt++) {
        const int n = n0c + wn*WN + nt*8 + (lid&3)*2;
        float2 bb = *(const float2*)(bias + n);
        float b0 = bb.x, b1 = bb.y;
        #pragma unroll
        for (int mt = 0; mt < 2; mt++) {
            #pragma unroll
            for (int half = 0; half < 2; half++) {
                const int m = m0 + wm*32 + mt*16 + (lid>>2) + half*8;
                float v0 = acc[mt][nt][half*2+0] + b0;
                float v1 = acc[mt][nt][half*2+1] + b1;
                if (RES) {
                    float2 r2 = *(const float2*)(resp + (size_t)m*NG + n);
                    v0 += r2.x; v1 += r2.y;
                }
                if (ACT == ACT_SWISH)    { v0 = f_swish(v0);    v1 = f_swish(v1); }
                if (WF32)
                    *(float2*)(outF + (size_t)m*NG + n) = make_float2(v0, v1);
                if (WBF) {
                    __nv_bfloat16 h0 = __float2bfloat16(v0);
                    __nv_bfloat16 h1 = __float2bfloat16(v1);
                    __nv_bfloat16 l0 = __float2bfloat16(v0 - __bfloat162float(h0));
                    __nv_bfloat16 l1 = __float2bfloat16(v1 - __bfloat162float(h1));
                    size_t pidx = ((size_t)m*NG + n) >> 1;
                    __nv_bfloat162 hp; hp.x = h0; hp.y = h1;
                    __nv_bfloat162 lp; lp.x = l0; lp.y = l1;
                    outBh[pidx] = hp;
                    outBl[pidx] = lp;
                }
            }
        }
    }
}

// ---------------------------------------------------------------------------
// Encoder tail: one kernel for mu / s / z0.  grid (128, 3), BN=64.
// ---------------------------------------------------------------------------
__global__ void __launch_bounds__(256,2) tail_k(
    const __nv_bfloat16* __restrict__ Ah_g, const __nv_bfloat16* __restrict__ Al_g,
    const __nv_bfloat16* __restrict__ wlat_h, const __nv_bfloat16* __restrict__ wlat_l,
    const float* __restrict__ b_lat,
    const __nv_bfloat16* __restrict__ winit_h, const __nv_bfloat16* __restrict__ winit_l,
    const float* __restrict__ b_init,
    float* __restrict__ out)
{
    constexpr int K = 256;
    constexpr int AHo = 0, ALo = 16384, BHo = 32768, BLo = 32768 + 8192;
    extern __shared__ char sm[];
    const int tid = threadIdx.x, lid = tid & 31, wid = tid >> 5;
    const int wm = wid & 3, wn = wid >> 2;
    const int m0 = blockIdx.x * 128;
    const int y  = blockIdx.y;
    const uint32_t sb = smem_u32(sm);

    const __nv_bfloat16 *Bh, *Bl;
    const float* bias;
    int stride;
    float* outp;
    if (y == 0)      { Bh = wlat_h;      Bl = wlat_l;      bias = b_lat;      stride = 128; outp = out; }
    else if (y == 1) { Bh = wlat_h + 64; Bl = wlat_l + 64; bias = b_lat + 64; stride = 128; outp = out + OUT_S_OFF; }
    else             { Bh = winit_h;     Bl = winit_l;     bias = b_init;     stride = 64;  outp = out + OUT_Z_OFF; }

    float acc[2][4][4];
    #pragma unroll
    for (int j=0;j<4;j++)
        #pragma unroll
        for (int q=0;q<4;q++){ acc[0][j][q]=0.0f; acc[1][j][q]=0.0f; }

    for (int c = 0; c < 4; c++) {
        const int c64 = c * 64;
        if (c) __syncthreads();
        #pragma unroll
        for (int it = 0; it < 4; it++) {
            int g = tid + it*256;
            int row = g >> 3, gg = g & 7;
            uint32_t off = (uint32_t)(row*128 + gg*16); off ^= (off>>3)&0x70;
            size_t src = (size_t)(m0+row)*K + c64 + gg*8;
            *(uint4*)(sm + AHo + off) = *(const uint4*)(Ah_g + src);
            *(uint4*)(sm + ALo + off) = *(const uint4*)(Al_g + src);
        }
        #pragma unroll
        for (int it = 0; it < 2; it++) {
            int g = tid + it*256;
            int row = g >> 3, gg = g & 7;
            uint32_t off = (uint32_t)(row*128 + gg*16); off ^= (off>>3)&0x70;
            size_t src = (size_t)(c64+row)*stride + gg*8;
            *(uint4*)(sm + BHo + off) = *(const uint4*)(Bh + src);
            *(uint4*)(sm + BLo + off) = *(const uint4*)(Bl + src);
        }
        __syncthreads();
        mma_block<2>(acc, sb+AHo, sb+ALo, sb+BHo, sb+BLo, wm, wn*32, lid);
    }

    #pragma unroll
    for (int nt = 0; nt < 4; nt++) {
        const int n = wn*32 + nt*8 + (lid&3)*2;
        float2 bb = *(const float2*)(bias + n);
        #pragma unroll
        for (int mt = 0; mt < 2; mt++) {
            #pragma unroll
            for (int half = 0; half < 2; half++) {
                const int m = m0 + wm*32 + mt*16 + (lid>>2) + half*8;
                float v0 = acc[mt][nt][half*2+0] + bb.x;
                float v1 = acc[mt][nt][half*2+1] + bb.y;
                if (y == 1) { v0 = __expf(0.5f*v0); v1 = __expf(0.5f*v1); }
                *(float2*)(outp + (size_t)m*64 + n) = make_float2(v0, v1);
            }
        }
    }
}

// ---------------------------------------------------------------------------
// dg1_k: only used ONCE (k=0) to produce h1 from z0.
// ---------------------------------------------------------------------------
__global__ void __launch_bounds__(256,2) dg1_k(
    const float* __restrict__ Zsrc,
    const __nv_bfloat16* __restrict__ Bh_g, const __nv_bfloat16* __restrict__ Bl_g,
    const float* __restrict__ bias512, const float* __restrict__ w0512,
    const float* __restrict__ ts, int kstep,
    __nv_bfloat162* __restrict__ outDh, __nv_bfloat162* __restrict__ outDl,
    __nv_bfloat162* __restrict__ outGh, __nv_bfloat162* __restrict__ outGl)
{
    constexpr int NG = 512;
    constexpr int AHo=0, ALo=16384, BHo=32768, BLo=49152;
    extern __shared__ char sm[];
    const int tid=threadIdx.x, lid=tid&31, wid=tid>>5;
    const int wm=wid&3, wn=wid>>2;
    const int m0 = blockIdx.x*128;
    const int n0c = blockIdx.y*128;
    const uint32_t sb = smem_u32(sm);

    float acc[2][8][4];
    #pragma unroll
    for (int i=0;i<2;i++)
        #pragma unroll
        for (int j=0;j<8;j++)
            #pragma unroll
            for (int q=0;q<4;q++) acc[i][j][q]=0.0f;

    #pragma unroll
    for (int it = 0; it < 4; it++) {
        int g = tid + it*256;
        int row = g >> 4, gg = g & 15;
        int sbt = gg >> 3, gin = gg & 7;
        uint32_t off = (uint32_t)(row*128 + gin*16);
        off ^= (off >> 3) & 0x70;
        off += (uint32_t)sbt * 8192;
        size_t src = (size_t)row*NG + n0c + gg*8;
        cpa16(sb + BHo + off, Bh_g + src);
        cpa16(sb + BLo + off, Bl_g + src);
    }
    CP_COMMIT();

    #pragma unroll
    for (int it = 0; it < 4; it++) {
        int g = tid + it*256;
        int row = g >> 3, gg = g & 7;
        uint32_t off = (uint32_t)(row*128 + gg*16);
        off ^= (off >> 3) & 0x70;
        const float* zp = Zsrc + (size_t)(m0+row)*64 + gg*8;
        float4 f0 = *(const float4*)zp;
        float4 f1 = *(const float4*)(zp+4);
        float fv[8] = {f0.x,f0.y,f0.z,f0.w,f1.x,f1.y,f1.z,f1.w};
        alignas(16) __nv_bfloat16 hv[8], lv[8];
        #pragma unroll
        for (int j=0;j<8;j++){
            __nv_bfloat16 h = __float2bfloat16(fv[j]);
            hv[j]=h; lv[j]=__float2bfloat16(fv[j]-__bfloat162float(h));
        }
        *(uint4*)(sm + AHo + off) = *(const uint4*)hv;
        *(uint4*)(sm + ALo + off) = *(const uint4*)lv;
    }
    CP_WAIT(0);
    __syncthreads();

    mma_block<4>(acc, sb+AHo, sb+ALo, sb+BHo, sb+BLo, wm, wn*64, lid);

    const bool isg = (n0c >= 256);
    __nv_bfloat162* oh = isg ? outGh : outDh;
    __nv_bfloat162* ol = isg ? outGl : outDl;
    const int nsub = isg ? 256 : 0;
    const float tval = __ldg(&ts[kstep]);

    #pragma unroll
    for (int nt = 0; nt < 8; nt++) {
        const int n = n0c + wn*64 + nt*8 + (lid&3)*2;
        float2 bb = *(const float2*)(bias512 + n);
        float2 w0 = *(const float2*)(w0512 + n);
        float b0 = fmaf(tval, w0.x, bb.x);
        float b1 = fmaf(tval, w0.y, bb.y);
        #pragma unroll
        for (int mt = 0; mt < 2; mt++) {
            #pragma unroll
            for (int half = 0; half < 2; half++) {
                const int m = m0 + wm*32 + mt*16 + (lid>>2) + half*8;
                float v0 = f_swish(acc[mt][nt][half*2+0] + b0);
                float v1 = f_swish(acc[mt][nt][half*2+1] + b1);
                __nv_bfloat16 h0 = __float2bfloat16(v0);
                __nv_bfloat16 h1 = __float2bfloat16(v1);
                __nv_bfloat16 l0 = __float2bfloat16(v0 - __bfloat162float(h0));
                __nv_bfloat16 l1 = __float2bfloat16(v1 - __bfloat162float(h1));
                size_t pidx = ((size_t)m*256 + (n - nsub)) >> 1;
                __nv_bfloat162 hp; hp.x = h0; hp.y = h1;
                __nv_bfloat162 lp; lp.x = l0; lp.y = l1;
                oh[pidx] = hp;
                ol[pidx] = lp;
            }
        }
    }
}

// ---------------------------------------------------------------------------
// SCAN step kernel (512 threads): d2 -> d3 -> g2 -> Euler -> h1(k+1).
// ---------------------------------------------------------------------------
__global__ void __launch_bounds__(512,1) d23g2_k(
    const __nv_bfloat16* __restrict__ Ah_g, const __nv_bfloat16* __restrict__ Al_g,
    const __nv_bfloat16* __restrict__ Wd2h, const __nv_bfloat16* __restrict__ Wd2l,
    const float* __restrict__ bd2,
    const __nv_bfloat16* __restrict__ Gh, const __nv_bfloat16* __restrict__ Gl,
    const __nv_bfloat16* __restrict__ Wd3h, const __nv_bfloat16* __restrict__ Wd3l,
    const float* __restrict__ bd3,
    const __nv_bfloat16* __restrict__ Wg2h, const __nv_bfloat16* __restrict__ Wg2l,
    const float* __restrict__ bg2,
    const float* __restrict__ Zsrc, const float* __restrict__ ts, int kstep,
    const float* __restrict__ noise, float* __restrict__ zout,
    const __nv_bfloat16* __restrict__ wdgh, const __nv_bfloat16* __restrict__ wdgl,
    const float* __restrict__ bdg, const float* __restrict__ w0dg,
    int do_h1,
    __nv_bfloat162* __restrict__ outDh, __nv_bfloat162* __restrict__ outDl,
    __nv_bfloat162* __restrict__ outGh, __nv_bfloat162* __restrict__ outGl)
{
    extern __shared__ char sm[];
    const int tid=threadIdx.x, lid=tid&31, wid=tid>>5;
    const int wm=wid&3, wn=wid>>2;
    const int m0 = blockIdx.x*128;
    const uint32_t sb = smem_u32(sm);

    auto load_Wd3 = [&](int c, int s){
        const uint32_t stb = sb + 196608u + (uint32_t)s*16384u;
        int row = tid>>3, gg = tid&7;
        uint32_t off = (uint32_t)(row*128 + gg*16); off ^= (off>>3)&0x70;
        size_t src = (size_t)(c*64+row)*64 + gg*8;
        cpa16(stb + 0    + off, Wd3h + src);
        cpa16(stb + 8192 + off, Wd3l + src);
        CP_COMMIT();
    };

    auto load_g2 = [&](int c, int s){
        const uint32_t stb = sb + 131072u + (uint32_t)s*49152u;
        const int c64 = c*64;
        #pragma unroll
        for (int it=0; it<2; it++){
            int g = tid + it*512;
            int row = g>>3, gg = g&7;
            uint32_t off = (uint32_t)(row*128 + gg*16); off ^= (off>>3)&0x70;
            size_t src = (size_t)(m0+row)*256 + c64 + gg*8;
            cpa16(stb + 0     + off, Gh + src);
            cpa16(stb + 16384 + off, Gl + src);
        }
        {
            int row = tid>>3, gg = tid&7;
            uint32_t off = (uint32_t)(row*128 + gg*16); off ^= (off>>3)&0x70;
            size_t src = (size_t)(c64+row)*64 + gg*8;
            cpa16(stb + 32768 + off, Wg2h + src);
            cpa16(stb + 40960 + off, Wg2l + src);
        }
        CP_COMMIT();
    };

    auto load_Wdg = [&](){
        #pragma unroll
        for (int it=0; it<8; it++){
            int g = tid + it*512;
            int row = g>>6, gg = g&63;
            int sbt = gg>>3, gin = gg&7;
            uint32_t off = (uint32_t)(row*128 + gin*16); off ^= (off>>3)&0x70;
            off += (uint32_t)sbt*8192;
            size_t src = (size_t)row*512 + gg*8;
            cpa16(sb + 32768 + off, wdgh + src);
            cpa16(sb + 98304 + off, wdgl + src);
        }
        CP_COMMIT();
    };

    // ======== phase 1: d2 ========
    {
        constexpr int SST = 98304;
        constexpr int AHo=0, ALo=16384, BHo=32768, BLo=65536;

        float acc[2][8][4];
        #pragma unroll
        for (int i=0;i<2;i++)
            #pragma unroll
            for (int j=0;j<8;j++)
                #pragma unroll
                for (int q=0;q<4;q++) acc[i][j][q]=0.0f;

        auto load_chunk = [&](int c, int s){
            const uint32_t stb = sb + (uint32_t)s*SST;
            const int c64 = c*64;
            #pragma unroll
            for (int it=0; it<2; it++){
                int g = tid + it*512;
                int row = g>>3, gg = g&7;
                uint32_t off = (uint32_t)(row*128 + gg*16); off ^= (off>>3)&0x70;
                size_t src = (size_t)(m0+row)*256 + c64 + gg*8;
                cpa16(stb + AHo + off, Ah_g + src);
                cpa16(stb + ALo + off, Al_g + src);
            }
            #pragma unroll
            for (int it=0; it<4; it++){
                int g = tid + it*512;
                int row = g>>5, gg = g&31;
                int sbt = gg>>3, gin = gg&7;
                uint32_t off = (uint32_t)(row*128 + gin*16); off ^= (off>>3)&0x70;
                off += (uint32_t)sbt*8192;
                size_t src = (size_t)(c64+row)*256 + gg*8;
                cpa16(stb + BHo + off, Wd2h + src);
                cpa16(stb + BLo + off, Wd2l + src);
            }
            CP_COMMIT();
        };

        load_chunk(0, 0);
        load_Wd3(0, 0);
        for (int c = 0; c < 4; c++) {
            if (c+1 < 4) { load_chunk(c+1, (c+1)&1); CP_WAIT(1); }
            else         { CP_WAIT(0); }
            __syncthreads();
            const uint32_t stb = sb + (uint32_t)(c&1)*SST;
            mma_block<4>(acc, stb+AHo, stb+ALo, stb+BHo, stb+BLo, wm, wn*64, lid);
            __syncthreads();
        }

        #pragma unroll
        for (int nt = 0; nt < 8; nt++) {
            const int n = wn*64 + nt*8 + (lid&3)*2;
            float2 bb = *(const float2*)(bd2 + n);
            const int ck = n >> 6;
            #pragma unroll
            for (int mt = 0; mt < 2; mt++) {
                #pragma unroll
                for (int half = 0; half < 2; half++) {
                    const int r = wm*32 + mt*16 + (lid>>2) + half*8;
                    float v0 = f_swish(acc[mt][nt][half*2+0] + bb.x);
                    float v1 = f_swish(acc[mt][nt][half*2+1] + bb.y);
                    __nv_bfloat16 h0 = __float2bfloat16(v0);
                    __nv_bfloat16 h1 = __float2bfloat16(v1);
                    __nv_bfloat16 l0 = __float2bfloat16(v0 - __bfloat162float(h0));
                    __nv_bfloat16 l1 = __float2bfloat16(v1 - __bfloat162float(h1));
                    uint32_t off = (uint32_t)(r*128 + (n&63)*2); off ^= (off>>3)&0x70;
                    __nv_bfloat162 hp; hp.x=h0; hp.y=h1;
                    __nv_bfloat162 lp; lp.x=l0; lp.y=l1;
                    *(__nv_bfloat162*)(sm + ck*16384 + off) = hp;
                    *(__nv_bfloat162*)(sm + 65536 + ck*16384 + off) = lp;
                }
            }
        }
        __syncthreads();
    }

    // ======== phase 2: d3 ========
    float accD[2][2][4];
    #pragma unroll
    for (int j=0;j<2;j++)
        #pragma unroll
        for (int q=0;q<4;q++){ accD[0][j][q]=0.0f; accD[1][j][q]=0.0f; }
    {
        load_g2(0, 0);
        for (int c = 0; c < 4; c++) {
            if (c+1 < 4) { load_Wd3(c+1, (c+1)&1); CP_WAIT(1); }
            else         { CP_WAIT(0); }
            __syncthreads();
            const uint32_t wstb = sb + 196608u + (uint32_t)(c&1)*16384u;
            mma_block<1>(accD, sb + (uint32_t)c*16384u, sb + 65536u + (uint32_t)c*16384u,
                         wstb, wstb + 8192u, wm, wn*16, lid);
            __syncthreads();
        }
    }

    // ======== phase 3: g2 (Wdg prefetch on the last chunk) ========
    float accG[2][2][4];
    #pragma unroll
    for (int j=0;j<2;j++)
        #pragma unroll
        for (int q=0;q<4;q++){ accG[0][j][q]=0.0f; accG[1][j][q]=0.0f; }
    {
        for (int c = 0; c < 4; c++) {
            if (c+1 < 4) { load_g2(c+1, (c+1)&1); CP_WAIT(1); }
            else {
                if (do_h1) { load_Wdg(); CP_WAIT(1); }
                else       { CP_WAIT(0); }
            }
            __syncthreads();
            const uint32_t stb = sb + 131072u + (uint32_t)(c&1)*49152u;
            mma_block<1>(accG, stb, stb+16384u, stb+32768u, stb+40960u, wm, wn*16, lid);
            __syncthreads();
        }
    }

    // ======== phase 4: Euler-Maruyama update (+ z_new split to smem) ========
    const float t0 = __ldg(&ts[kstep]);
    const float t1 = __ldg(&ts[kstep+1]);
    const float dt = t1 - t0;
    const float sq = sqrtf(dt);
    const float* noise_k = noise + (size_t)kstep*ZSLICE;

    #pragma unroll
    for (int nt = 0; nt < 2; nt++) {
        const int n = wn*16 + nt*8 + (lid&3)*2;
        float2 bd = *(const float2*)(bd3 + n);
        float2 bg = *(const float2*)(bg2 + n);
        #pragma unroll
        for (int mt = 0; mt < 2; mt++) {
            #pragma unroll
            for (int half = 0; half < 2; half++) {
                const int r = wm*32 + mt*16 + (lid>>2) + half*8;
                const int m = m0 + r;
                float d0 = accD[mt][nt][half*2+0] + bd.x;
                float d1 = accD[mt][nt][half*2+1] + bd.y;
                float g0 = f_softplus(accG[mt][nt][half*2+0] + bg.x);
                float g1 = f_softplus(accG[mt][nt][half*2+1] + bg.y);
                size_t idx = (size_t)m*64 + n;
                float2 zz = *(const float2*)(Zsrc + idx);
                float2 nn = *(const float2*)(noise_k + idx);
                float z0 = zz.x + d0*dt + g0*sq*nn.x;
                float z1 = zz.y + d1*dt + g1*sq*nn.y;
                *(float2*)(zout + idx) = make_float2(z0, z1);
                if (do_h1) {
                    __nv_bfloat16 h0 = __float2bfloat16(z0);
                    __nv_bfloat16 h1 = __float2bfloat16(z1);
                    __nv_bfloat16 l0 = __float2bfloat16(z0 - __bfloat162float(h0));
                    __nv_bfloat16 l1 = __float2bfloat16(z1 - __bfloat162float(h1));
                    uint32_t off = (uint32_t)(r*128 + n*2); off ^= (off>>3)&0x70;
                    __nv_bfloat162 hp; hp.x=h0; hp.y=h1;
                    __nv_bfloat162 lp; lp.x=l0; lp.y=l1;
                    *(__nv_bfloat162*)(sm + off) = hp;
                    *(__nv_bfloat162*)(sm + 16384 + off) = lp;
                }
            }
        }
    }

    // ======== phase 5: h1(k+1) = swish([t1, z_new] @ [Wd1|Wg1]) ========
    if (do_h1) {
        CP_WAIT(0);
        __syncthreads();
        #pragma unroll
        for (int hb = 0; hb < 2; hb++) {
            float acc5[2][8][4];
            #pragma unroll
            for (int j=0;j<8;j++)
                #pragma unroll
                for (int q=0;q<4;q++){ acc5[0][j][q]=0.0f; acc5[1][j][q]=0.0f; }

            mma_block<4>(acc5, sb, sb+16384u,
                         sb+32768u + (uint32_t)hb*32768u,
                         sb+98304u + (uint32_t)hb*32768u, wm, wn*64, lid);

            __nv_bfloat162* oh = hb ? outGh : outDh;
            __nv_bfloat162* ol = hb ? outGl : outDl;
            #pragma unroll
            for (int nt = 0; nt < 8; nt++) {
                const int nl = wn*64 + nt*8 + (lid&3)*2;
                const int ng = hb*256 + nl;
                float2 bb = *(const float2*)(bdg + ng);
                float2 w0 = *(const float2*)(w0dg + ng);
                float b0 = fmaf(t1, w0.x, bb.x);
                float b1 = fmaf(t1, w0.y, bb.y);
                #pragma unroll
                for (int mt = 0; mt < 2; mt++) {
                    #pragma unroll
                    for (int half = 0; half < 2; half++) {
                        const int m = m0 + wm*32 + mt*16 + (lid>>2) + half*8;
                        float v0 = f_swish(acc5[mt][nt][half*2+0] + b0);
                        float v1 = f_swish(acc5[mt][nt][half*2+1] + b1);
                        __nv_bfloat16 h0 = __float2bfloat16(v0);
                        __nv_bfloat16 h1 = __float2bfloat16(v1);
                        __nv_bfloat16 l0 = __float2bfloat16(v0 - __bfloat162float(h0));
                        __nv_bfloat16 l1 = __float2bfloat16(v1 - __bfloat162float(h1));
                        size_t pidx = ((size_t)m*256 + nl) >> 1;
                        __nv_bfloat162 hp; hp.x=h0; hp.y=h1;
                        __nv_bfloat162 lp; lp.x=l0; lp.y=l1;
                        oh[pidx] = hp;
                        ol[pidx] = lp;
                    }
                }
            }
        }
    }
}

// ---------------- prep: ALL elementwise splits in ONE kernel ----------------
// idx layout: [0, 4194304) = x ; then weight groups appended in fixed order.
#define PREP_TOTAL (4194304 + 671744)
__global__ void prep_all(
    const float* __restrict__ x,
    const float* __restrict__ W_in, const float* __restrict__ Wb1,
    const float* __restrict__ Wb2,  const float* __restrict__ W_fo,
    const float* __restrict__ W_lat,const float* __restrict__ W_init,
    const float* __restrict__ Wd2,  const float* __restrict__ Wd3,
    const float* __restrict__ Wg2,
    __nv_bfloat16* __restrict__ xh, __nv_bfloat16* __restrict__ xl,
    __nv_bfloat16* __restrict__ wh, __nv_bfloat16* __restrict__ wl)
{
    int i = blockIdx.x * 256 + threadIdx.x;
    float v;
    __nv_bfloat16 *dh, *dl;
    if (i < 4194304) {
        v = x[i]; dh = xh + i; dl = xl + i;
    } else {
        int j = i - 4194304;
        const float* s; int base;
        if      (j < 65536)            { s = W_in;   base = OFF_WIN;   }
        else if ((j -= 65536) < 196608){ s = Wb1;    base = OFF_WB1;   }
        else if ((j -= 196608) < 196608){ s = Wb2;   base = OFF_WB2;   }
        else if ((j -= 196608) < 65536){ s = W_fo;   base = OFF_WFO;   }
        else if ((j -= 65536) < 32768) { s = W_lat;  base = OFF_WLAT;  }
        else if ((j -= 32768) < 16384) { s = W_init; base = OFF_WINIT; }
        else if ((j -= 16384) < 65536) { s = Wd2;    base = OFF_WD2;   }
        else if ((j -= 65536) < 16384) { s = Wd3;    base = OFF_WD3;   }
        else                           { j -= 16384; s = Wg2; base = OFF_WG2; }
        v = s[j]; dh = wh + base + j; dl = wl + base + j;
    }
    __nv_bfloat16 h = __float2bfloat16(v);
    *dh = h;
    *dl = __float2bfloat16(v - __bfloat162float(h));
}

__global__ void prep_dg1(const float* __restrict__ Wd1, const float* __restrict__ Wg1,
                         const float* __restrict__ bd1, const float* __restrict__ bg1,
                         __nv_bfloat16* __restrict__ wh, __nv_bfloat16* __restrict__ wl,
                         float* __restrict__ bias, float* __restrict__ w0)
{
    int idx = blockIdx.x * 256 + threadIdx.x;   // 64*512
    int k = idx >> 9, n = idx & 511;
    float v = (n < 256) ? Wd1[(size_t)(k+1)*256 + n] : Wg1[(size_t)(k+1)*256 + (n-256)];
    __nv_bfloat16 h = __float2bfloat16(v);
    wh[idx] = h;
    wl[idx] = __float2bfloat16(v - __bfloat162float(h));
    if (idx < 512) {
        bias[idx] = (idx < 256) ? bd1[idx] : bg1[idx-256];
        w0[idx]   = (idx < 256) ? Wd1[idx] : Wg1[idx-256];
    }
}

// ---------------------------------------------------------------------------
extern "C" void kernel_launch(void* const* d_in, const int* in_sizes, int n_in,
                              void* d_out, int out_size)
{
    const float* x     = (const float*)d_in[0];
    const float* ts    = (const float*)d_in[1];
    const float* noise = (const float*)d_in[2];
    const float* W_in  = (const float*)d_in[3];
    const float* b_in  = (const float*)d_in[4];
    const float* Wb1   = (const float*)d_in[5];
    const float* bb1   = (const float*)d_in[6];
    const float* Wb2   = (const float*)d_in[7];
    const float* bb2   = (const float*)d_in[8];
    const float* W_fo  = (const float*)d_in[9];
    const float* b_fo  = (const float*)d_in[10];
    const float* W_lat = (const float*)d_in[11];
    const float* b_lat = (const float*)d_in[12];
    const float* W_init= (const float*)d_in[13];
    const float* b_init= (const float*)d_in[14];
    const float* Wd1   = (const float*)d_in[15];
    const float* bd1   = (const float*)d_in[16];
    const float* Wd2   = (const float*)d_in[17];
    const float* bd2   = (const float*)d_in[18];
    const float* Wd3   = (const float*)d_in[19];
    const float* bd3   = (const float*)d_in[20];
    const float* Wg1   = (const float*)d_in[21];
    const float* bg1   = (const float*)d_in[22];
    const float* Wg2   = (const float*)d_in[23];
    const float* bg2   = (const float*)d_in[24];
    float* out = (float*)d_out;

    __nv_bfloat16 *xh, *xl, *ah, *al, *bh, *bl, *gh, *gl, *wh, *wl, *wdgh, *wdgl;
    float *hres, *bdg, *w0dg;
    cudaGetSymbolAddress((void**)&xh,  g_xh);
    cudaGetSymbolAddress((void**)&xl,  g_xl);
    cudaGetSymbolAddress((void**)&ah,  g_ah);
    cudaGetSymbolAddress((void**)&al,  g_al);
    cudaGetSymbolAddress((void**)&bh,  g_bh);
    cudaGetSymbolAddress((void**)&bl,  g_bl);
    cudaGetSymbolAddress((void**)&gh,  g_gh);
    cudaGetSymbolAddress((void**)&gl,  g_gl);
    cudaGetSymbolAddress((void**)&wh,  g_wh);
    cudaGetSymbolAddress((void**)&wl,  g_wl);
    cudaGetSymbolAddress((void**)&wdgh,g_wdgh);
    cudaGetSymbolAddress((void**)&wdgl,g_wdgl);
    cudaGetSymbolAddress((void**)&hres,g_hres);
    cudaGetSymbolAddress((void**)&bdg, g_bdg);
    cudaGetSymbolAddress((void**)&w0dg,g_w0dg);

    // ---- prep: 2 launches total ----
    prep_all<<<PREP_TOTAL/256, 256>>>(x, W_in, Wb1, Wb2, W_fo, W_lat, W_init,
                                      Wd2, Wd3, Wg2, xh, xl, wh, wl);
    prep_dg1<<<128, 256>>>(Wd1, Wg1, bd1, bg1, wdgh, wdgl, bdg, w0dg);

    // ---- encoder kernel handles ----
    auto* kIN  = mgemm<256,256,ACT_SWISH, false,true, true >;
    auto* kB1  = mgemm<256,256,ACT_SWISH, false,true, false>;
    auto* kB2  = mgemm<256,256,ACT_NONE,  true, true, true >;
    auto* kFO  = mgemm<256,256,ACT_NONE,  false,true, false>;

    const int SM128 = 32768 + 2*128*128;   // 65536
    const int SM64  = 32768 + 2*64*128;    // 49152
    cudaFuncSetAttribute((const void*)kIN,  cudaFuncAttributeMaxDynamicSharedMemorySize, SM128);
    cudaFuncSetAttribute((const void*)kB1,  cudaFuncAttributeMaxDynamicSharedMemorySize, SM128);
    cudaFuncSetAttribute((const void*)kB2,  cudaFuncAttributeMaxDynamicSharedMemorySize, SM128);
    cudaFuncSetAttribute((const void*)kFO,  cudaFuncAttributeMaxDynamicSharedMemorySize, SM128);
    cudaFuncSetAttribute((const void*)tail_k,  cudaFuncAttributeMaxDynamicSharedMemorySize, SM64);
    cudaFuncSetAttribute((const void*)dg1_k,   cudaFuncAttributeMaxDynamicSharedMemorySize, 65536);
    cudaFuncSetAttribute((const void*)d23g2_k, cudaFuncAttributeMaxDynamicSharedMemorySize, 229376);

    dim3 blk(256);
    dim3 gN256(BATCH/128, 2);

    __nv_bfloat162 *ah2 = (__nv_bfloat162*)ah, *al2 = (__nv_bfloat162*)al;
    __nv_bfloat162 *bh2 = (__nv_bfloat162*)bh, *bl2 = (__nv_bfloat162*)bl;
    __nv_bfloat162 *gh2 = (__nv_bfloat162*)gh, *gl2 = (__nv_bfloat162*)gl;

    // ---- encoder ----
    kIN<<<gN256, blk, SM128>>>(xh, xl, wh+OFF_WIN, wl+OFF_WIN, b_in,
                               nullptr, hres, ah2, al2);
    for (int i = 0; i < 3; i++) {
        kB1<<<gN256, blk, SM128>>>(ah, al, wh+OFF_WB1+i*65536, wl+OFF_WB1+i*65536,
                                   bb1 + i*HID, nullptr, nullptr, bh2, bl2);
        kB2<<<gN256, blk, SM128>>>(bh, bl, wh+OFF_WB2+i*65536, wl+OFF_WB2+i*65536,
                                   bb2 + i*HID, hres, hres, ah2, al2);
    }
    kFO<<<gN256, blk, SM128>>>(ah, al, wh+OFF_WFO, wl+OFF_WFO, b_fo,
                               nullptr, nullptr, bh2, bl2);
    tail_k<<<dim3(BATCH/128, 3), blk, SM64>>>(bh, bl,
                                              wh+OFF_WLAT, wl+OFF_WLAT, b_lat,
                                              wh+OFF_WINIT, wl+OFF_WINIT, b_init,
                                              out);

    // ---- SDE scan: dg1 once for z0, then 1 kernel/step ----
    dg1_k<<<dim3(BATCH/128, 4), blk, 65536>>>(out + OUT_Z_OFF, wdgh, wdgl, bdg, w0dg,
                                              ts, 0, ah2, al2, gh2, gl2);
    for (int k = 0; k < NSTEP; k++) {
        const float* z = out + OUT_Z_OFF + (size_t)k * ZSLICE;
        float* zn = out + OUT_Z_OFF + (size_t)(k+1) * ZSLICE;
        d23g2_k<<<dim3(BATCH/128, 1), dim3(512), 229376>>>(
            ah, al, wh+OFF_WD2, wl+OFF_WD2, bd2,
            gh, gl, wh+OFF_WD3, wl+OFF_WD3, bd3,
            wh+OFF_WG2, wl+OFF_WG2, bg2,
            z, ts, k, noise, zn,
            wdgh, wdgl, bdg, w0dg, (k+1 < NSTEP) ? 1 : 0,
            ah2, al2, gh2, gl2);
    }
}

// round 16
// speedup vs baseline: 1.0075x; 1.0075x over previous
#include <cuda_runtime.h>
#include <cuda_bf16.h>
#include <stdint.h>
#include <math.h>

#define BATCH 16384
#define HID   256
#define LATD  64
#define NSTEP 63

#define OUT_S_OFF  (BATCH*LATD)
#define OUT_Z_OFF  (2*BATCH*LATD)
#define ZSLICE     (BATCH*LATD)

// ---------------- scratch (static device arrays; no allocation) ----------------
__device__ __nv_bfloat16 g_xh[BATCH*HID], g_xl[BATCH*HID];
__device__ __nv_bfloat16 g_ah[BATCH*HID], g_al[BATCH*HID];
__device__ __nv_bfloat16 g_bh[BATCH*HID], g_bl[BATCH*HID];
__device__ __nv_bfloat16 g_gh[BATCH*HID], g_gl[BATCH*HID];
__device__ float g_hres[BATCH*HID];

// combined [Wd1|Wg1] weights: [64][512]
__device__ __nv_bfloat16 g_wdgh[64*512], g_wdgl[64*512];
__device__ float g_bdg[512], g_w0dg[512];

// weight scratch: elementwise hi/lo split, natural [K][N] layout
#define OFF_WIN   0
#define OFF_WB1   65536
#define OFF_WB2   (OFF_WB1 + 3*65536)
#define OFF_WFO   (OFF_WB2 + 3*65536)
#define OFF_WLAT  (OFF_WFO + 65536)
#define OFF_WINIT (OFF_WLAT + 32768)
#define OFF_WD2   (OFF_WINIT + 16384)
#define OFF_WD3   (OFF_WD2 + 65536)
#define OFF_WG2   (OFF_WD3 + 16384)
#define WT_TOTAL  (OFF_WG2 + 16384)

__device__ __nv_bfloat16 g_wh[WT_TOTAL];
__device__ __nv_bfloat16 g_wl[WT_TOTAL];

enum { ACT_NONE=0, ACT_SWISH=1, ACT_SOFTPLUS=2 };

__device__ __forceinline__ float f_swish(float v){
    return v * (1.0f / (1.0f + __expf(-v)));
}
__device__ __forceinline__ float f_softplus(float v){
    return fmaxf(v, 0.0f) + log1pf(__expf(-fabsf(v)));
}

__device__ __forceinline__ uint32_t smem_u32(const void* p){
    uint32_t a;
    asm("{ .reg .u64 t; cvta.to.shared.u64 t, %1; cvt.u32.u64 %0, t; }" : "=r"(a) : "l"(p));
    return a;
}
__device__ __forceinline__ void ldsm4(uint32_t (&r)[4], uint32_t addr){
    asm volatile("ldmatrix.sync.aligned.m8n8.x4.shared.b16 {%0,%1,%2,%3}, [%4];"
        : "=r"(r[0]),"=r"(r[1]),"=r"(r[2]),"=r"(r[3]) : "r"(addr));
}
__device__ __forceinline__ void ldsm4t(uint32_t (&r)[4], uint32_t addr){
    asm volatile("ldmatrix.sync.aligned.m8n8.x4.trans.shared.b16 {%0,%1,%2,%3}, [%4];"
        : "=r"(r[0]),"=r"(r[1]),"=r"(r[2]),"=r"(r[3]) : "r"(addr));
}
__device__ __forceinline__ void mma_bf16(float (&d)[4], const uint32_t (&a)[4],
                                         uint32_t b0, uint32_t b1){
    asm volatile(
        "mma.sync.aligned.m16n8k16.row.col.f32.bf16.bf16.f32 "
        "{%0,%1,%2,%3}, {%4,%5,%6,%7}, {%8,%9}, {%0,%1,%2,%3};"
        : "+f"(d[0]),"+f"(d[1]),"+f"(d[2]),"+f"(d[3])
        : "r"(a[0]),"r"(a[1]),"r"(a[2]),"r"(a[3]), "r"(b0),"r"(b1));
}
__device__ __forceinline__ void cpa16(uint32_t dst, const void* src){
    asm volatile("cp.async.cg.shared.global [%0], [%1], 16;" :: "r"(dst), "l"(src));
}
#define CP_COMMIT() asm volatile("cp.async.commit_group;" ::: "memory")
#define CP_WAIT(n)  asm volatile("cp.async.wait_group %0;" :: "n"(n) : "memory")

// ---------------------------------------------------------------------------
// Single-pass 3-product MMA block (Ah*Bh + Al*Bh + Ah*Bl).
// ---------------------------------------------------------------------------
template<int NP>
__device__ __forceinline__ void mma_block(
    float (&acc)[2][NP*2][4],
    uint32_t AHb, uint32_t ALb, uint32_t BHb, uint32_t BLb,
    int wm, int wnbase, int lid)
{
    #pragma unroll
    for (int kk = 0; kk < 4; kk++) {
        uint32_t a0h[4], a1h[4], a0l[4], a1l[4];
        {
            int row = wm*32 + (lid&7) + ((lid>>3)&1)*8;
            int gg  = kk*2 + (lid>>4);
            uint32_t off = (uint32_t)(row*128 + gg*16); off ^= (off>>3)&0x70;
            ldsm4(a0h, AHb + off);
            ldsm4(a0l, ALb + off);
            uint32_t off2 = (uint32_t)((row+16)*128 + gg*16); off2 ^= (off2>>3)&0x70;
            ldsm4(a1h, AHb + off2);
            ldsm4(a1l, ALb + off2);
        }
        const int krow = kk*16 + (lid&7) + ((lid>>3)&1)*8;
        #pragma unroll
        for (int np = 0; np < NP; np++) {
            int colb = wnbase + np*16;
            int sbt  = colb >> 6;
            int gg   = ((colb & 63) >> 3) + (lid>>4);
            uint32_t off = (uint32_t)(krow*128 + gg*16); off ^= (off>>3)&0x70;
            off += (uint32_t)sbt * 8192;
            uint32_t b[4], bl[4];
            ldsm4t(b,  BHb + off);
            ldsm4t(bl, BLb + off);
            mma_bf16(acc[0][np*2  ], a0h, b[0], b[1]);
            mma_bf16(acc[1][np*2  ], a1h, b[0], b[1]);
            mma_bf16(acc[0][np*2+1], a0h, b[2], b[3]);
            mma_bf16(acc[1][np*2+1], a1h, b[2], b[3]);
            mma_bf16(acc[0][np*2  ], a0l, b[0], b[1]);
            mma_bf16(acc[1][np*2  ], a1l, b[0], b[1]);
            mma_bf16(acc[0][np*2+1], a0l, b[2], b[3]);
            mma_bf16(acc[1][np*2+1], a1l, b[2], b[3]);
            mma_bf16(acc[0][np*2  ], a0h, bl[0], bl[1]);
            mma_bf16(acc[1][np*2  ], a1h, bl[0], bl[1]);
            mma_bf16(acc[0][np*2+1], a0h, bl[2], bl[3]);
            mma_bf16(acc[1][np*2+1], a1h, bl[2], bl[3]);
        }
    }
}

// ---------------------------------------------------------------------------
// (encoder first/last) mma.sync bf16 split GEMM.
// ---------------------------------------------------------------------------
template<int K, int NG, int ACT, bool RES, bool WBF, bool WF32>
__global__ void __launch_bounds__(256,2) mgemm(
    const __nv_bfloat16* __restrict__ Ah_g, const __nv_bfloat16* __restrict__ Al_g,
    const __nv_bfloat16* __restrict__ Bh_g, const __nv_bfloat16* __restrict__ Bl_g,
    const float* __restrict__ bias,
    const float* __restrict__ resp,
    float* __restrict__ outF,
    __nv_bfloat162* __restrict__ outBh, __nv_bfloat162* __restrict__ outBl)
{
    constexpr int BN  = (NG >= 128) ? 128 : 64;
    constexpr int WN  = BN / 2;
    constexpr int NP  = WN / 16;
    constexpr int NCH = K / 64;
    constexpr int BSZ = BN * 128;
    constexpr int AHo = 0, ALo = 16384, BHo = 32768, BLo = 32768 + BSZ;

    extern __shared__ char sm[];
    const int tid = threadIdx.x;
    const int lid = tid & 31, wid = tid >> 5;
    const int wm  = wid & 3;
    const int wn  = wid >> 2;
    const int m0  = blockIdx.x * 128;
    const int n0c = blockIdx.y * BN;
    const uint32_t sb = smem_u32(sm);

    float acc[2][NP*2][4];
    #pragma unroll
    for (int i=0;i<2;i++)
        #pragma unroll
        for (int j=0;j<NP*2;j++)
            #pragma unroll
            for (int q=0;q<4;q++) acc[i][j][q] = 0.0f;

    for (int c = 0; c < NCH; c++) {
        const int c64 = c * 64;
        if (c) __syncthreads();

        #pragma unroll
        for (int it = 0; it < 4; it++) {
            int g = tid + it*256;
            int row = g >> 3, gg = g & 7;
            uint32_t off = (uint32_t)(row*128 + gg*16);
            off ^= (off >> 3) & 0x70;
            size_t src = (size_t)(m0+row)*K + c64 + gg*8;
            *(uint4*)(sm + AHo + off) = *(const uint4*)(Ah_g + src);
            *(uint4*)(sm + ALo + off) = *(const uint4*)(Al_g + src);
        }
        #pragma unroll
        for (int it = 0; it < BN/32; it++) {
            int g = tid + it*256;
            int row, gg;
            if (BN == 128) { row = g >> 4; gg = g & 15; }
            else           { row = g >> 3; gg = g & 7;  }
            int s = gg >> 3, gin = gg & 7;
            uint32_t off = (uint32_t)(row*128 + gin*16);
            off ^= (off >> 3) & 0x70;
            off += (uint32_t)s * 8192;
            size_t src = (size_t)(c64+row)*NG + n0c + gg*8;
            *(uint4*)(sm + BHo + off) = *(const uint4*)(Bh_g + src);
            *(uint4*)(sm + BLo + off) = *(const uint4*)(Bl_g + src);
        }
        __syncthreads();

        mma_block<NP>(acc, sb+AHo, sb+ALo, sb+BHo, sb+BLo, wm, wn*WN, lid);
    }

    #pragma unroll
    for (int nt = 0; nt < NP*2; nt++) {
        const int n = n0c + wn*WN + nt*8 + (lid&3)*2;
        float2 bb = *(const float2*)(bias + n);
        float b0 = bb.x, b1 = bb.y;
        #pragma unroll
        for (int mt = 0; mt < 2; mt++) {
            #pragma unroll
            for (int half = 0; half < 2; half++) {
                const int m = m0 + wm*32 + mt*16 + (lid>>2) + half*8;
                float v0 = acc[mt][nt][half*2+0] + b0;
                float v1 = acc[mt][nt][half*2+1] + b1;
                if (RES) {
                    float2 r2 = *(const float2*)(resp + (size_t)m*NG + n);
                    v0 += r2.x; v1 += r2.y;
                }
                if (ACT == ACT_SWISH)    { v0 = f_swish(v0);    v1 = f_swish(v1); }
                if (WF32)
                    *(float2*)(outF + (size_t)m*NG + n) = make_float2(v0, v1);
                if (WBF) {
                    __nv_bfloat16 h0 = __float2bfloat16(v0);
                    __nv_bfloat16 h1 = __float2bfloat16(v1);
                    __nv_bfloat16 l0 = __float2bfloat16(v0 - __bfloat162float(h0));
                    __nv_bfloat16 l1 = __float2bfloat16(v1 - __bfloat162float(h1));
                    size_t pidx = ((size_t)m*NG + n) >> 1;
                    __nv_bfloat162 hp; hp.x = h0; hp.y = h1;
                    __nv_bfloat162 lp; lp.x = l0; lp.y = l1;
                    outBh[pidx] = hp;
                    outBl[pidx] = lp;
                }
            }
        }
    }
}

// ---------------------------------------------------------------------------
// Fused residual block (512 threads): h1 = swish(h@Wb1+b1) in smem,
// h_new = h1@Wb2 + b2 + hres  ->  hres(f32) and h split (in place).
// smem: phase A stages [0,196608) (2x96KB); h1 split [0,131072);
//       phase B W2 chunk @131072 (hi) / 163840 (lo).
// ---------------------------------------------------------------------------
__global__ void __launch_bounds__(512,1) blk_k(
    const __nv_bfloat16* __restrict__ Ah_g, const __nv_bfloat16* __restrict__ Al_g,
    const __nv_bfloat16* __restrict__ W1h, const __nv_bfloat16* __restrict__ W1l,
    const float* __restrict__ b1,
    const __nv_bfloat16* __restrict__ W2h, const __nv_bfloat16* __restrict__ W2l,
    const float* __restrict__ b2,
    float* __restrict__ hres,
    __nv_bfloat162* __restrict__ outAh, __nv_bfloat162* __restrict__ outAl)
{
    extern __shared__ char sm[];
    const int tid=threadIdx.x, lid=tid&31, wid=tid>>5;
    const int wm=wid&3, wn=wid>>2;
    const int m0 = blockIdx.x*128;
    const uint32_t sb = smem_u32(sm);

    // ======== phase A: h1 = swish(h @ W1 + b1), 2-stage pipeline ========
    {
        constexpr int SST = 98304;
        constexpr int AHo=0, ALo=16384, BHo=32768, BLo=65536;

        float acc[2][8][4];
        #pragma unroll
        for (int j=0;j<8;j++)
            #pragma unroll
            for (int q=0;q<4;q++){ acc[0][j][q]=0.0f; acc[1][j][q]=0.0f; }

        auto load_chunk = [&](int c, int s){
            const uint32_t stb = sb + (uint32_t)s*SST;
            const int c64 = c*64;
            #pragma unroll
            for (int it=0; it<2; it++){
                int g = tid + it*512;
                int row = g>>3, gg = g&7;
                uint32_t off = (uint32_t)(row*128 + gg*16); off ^= (off>>3)&0x70;
                size_t src = (size_t)(m0+row)*256 + c64 + gg*8;
                cpa16(stb + AHo + off, Ah_g + src);
                cpa16(stb + ALo + off, Al_g + src);
            }
            #pragma unroll
            for (int it=0; it<4; it++){
                int g = tid + it*512;
                int row = g>>5, gg = g&31;
                int sbt = gg>>3, gin = gg&7;
                uint32_t off = (uint32_t)(row*128 + gin*16); off ^= (off>>3)&0x70;
                off += (uint32_t)sbt*8192;
                size_t src = (size_t)(c64+row)*256 + gg*8;
                cpa16(stb + BHo + off, W1h + src);
                cpa16(stb + BLo + off, W1l + src);
            }
            CP_COMMIT();
        };

        load_chunk(0, 0);
        for (int c = 0; c < 4; c++) {
            if (c+1 < 4) { load_chunk(c+1, (c+1)&1); CP_WAIT(1); }
            else         { CP_WAIT(0); }
            __syncthreads();
            const uint32_t stb = sb + (uint32_t)(c&1)*SST;
            mma_block<4>(acc, stb+AHo, stb+ALo, stb+BHo, stb+BLo, wm, wn*64, lid);
            __syncthreads();
        }

        // h1 -> SMEM bf16 split, A-chunk format
        #pragma unroll
        for (int nt = 0; nt < 8; nt++) {
            const int n = wn*64 + nt*8 + (lid&3)*2;
            float2 bb = *(const float2*)(b1 + n);
            const int ck = n >> 6;
            #pragma unroll
            for (int mt = 0; mt < 2; mt++) {
                #pragma unroll
                for (int half = 0; half < 2; half++) {
                    const int r = wm*32 + mt*16 + (lid>>2) + half*8;
                    float v0 = f_swish(acc[mt][nt][half*2+0] + bb.x);
                    float v1 = f_swish(acc[mt][nt][half*2+1] + bb.y);
                    __nv_bfloat16 h0 = __float2bfloat16(v0);
                    __nv_bfloat16 h1 = __float2bfloat16(v1);
                    __nv_bfloat16 l0 = __float2bfloat16(v0 - __bfloat162float(h0));
                    __nv_bfloat16 l1 = __float2bfloat16(v1 - __bfloat162float(h1));
                    uint32_t off = (uint32_t)(r*128 + (n&63)*2); off ^= (off>>3)&0x70;
                    __nv_bfloat162 hp; hp.x=h0; hp.y=h1;
                    __nv_bfloat162 lp; lp.x=l0; lp.y=l1;
                    *(__nv_bfloat162*)(sm + ck*16384 + off) = hp;
                    *(__nv_bfloat162*)(sm + 65536 + ck*16384 + off) = lp;
                }
            }
        }
        __syncthreads();
    }

    // ======== phase B: h_new = h1 @ W2 + b2 + hres ========
    float acc[2][8][4];
    #pragma unroll
    for (int j=0;j<8;j++)
        #pragma unroll
        for (int q=0;q<4;q++){ acc[0][j][q]=0.0f; acc[1][j][q]=0.0f; }

    for (int c = 0; c < 4; c++) {
        // load W2 chunk c (64 rows x 256 cols, hi+lo = 64KB) into single stage
        #pragma unroll
        for (int it=0; it<4; it++){
            int g = tid + it*512;
            int row = g>>5, gg = g&31;
            int sbt = gg>>3, gin = gg&7;
            uint32_t off = (uint32_t)(row*128 + gin*16); off ^= (off>>3)&0x70;
            off += (uint32_t)sbt*8192;
            size_t src = (size_t)(c*64+row)*256 + gg*8;
            cpa16(sb + 131072 + off, W2h + src);
            cpa16(sb + 163840 + off, W2l + src);
        }
        CP_COMMIT(); CP_WAIT(0);
        __syncthreads();
        mma_block<4>(acc, sb + (uint32_t)c*16384u, sb + 65536u + (uint32_t)c*16384u,
                     sb + 131072u, sb + 163840u, wm, wn*64, lid);
        __syncthreads();
    }

    #pragma unroll
    for (int nt = 0; nt < 8; nt++) {
        const int n = wn*64 + nt*8 + (lid&3)*2;
        float2 bb = *(const float2*)(b2 + n);
        #pragma unroll
        for (int mt = 0; mt < 2; mt++) {
            #pragma unroll
            for (int half = 0; half < 2; half++) {
                const int m = m0 + wm*32 + mt*16 + (lid>>2) + half*8;
                float2 r2 = *(const float2*)(hres + (size_t)m*256 + n);
                float v0 = acc[mt][nt][half*2+0] + bb.x + r2.x;
                float v1 = acc[mt][nt][half*2+1] + bb.y + r2.y;
                *(float2*)(hres + (size_t)m*256 + n) = make_float2(v0, v1);
                __nv_bfloat16 h0 = __float2bfloat16(v0);
                __nv_bfloat16 h1 = __float2bfloat16(v1);
                __nv_bfloat16 l0 = __float2bfloat16(v0 - __bfloat162float(h0));
                __nv_bfloat16 l1 = __float2bfloat16(v1 - __bfloat162float(h1));
                size_t pidx = ((size_t)m*256 + n) >> 1;
                __nv_bfloat162 hp; hp.x = h0; hp.y = h1;
                __nv_bfloat162 lp; lp.x = l0; lp.y = l1;
                outAh[pidx] = hp;
                outAl[pidx] = lp;
            }
        }
    }
}

// ---------------------------------------------------------------------------
// Encoder tail: one kernel for mu / s / z0.  grid (128, 3), BN=64.
// ---------------------------------------------------------------------------
__global__ void __launch_bounds__(256,2) tail_k(
    const __nv_bfloat16* __restrict__ Ah_g, const __nv_bfloat16* __restrict__ Al_g,
    const __nv_bfloat16* __restrict__ wlat_h, const __nv_bfloat16* __restrict__ wlat_l,
    const float* __restrict__ b_lat,
    const __nv_bfloat16* __restrict__ winit_h, const __nv_bfloat16* __restrict__ winit_l,
    const float* __restrict__ b_init,
    float* __restrict__ out)
{
    constexpr int K = 256;
    constexpr int AHo = 0, ALo = 16384, BHo = 32768, BLo = 32768 + 8192;
    extern __shared__ char sm[];
    const int tid = threadIdx.x, lid = tid & 31, wid = tid >> 5;
    const int wm = wid & 3, wn = wid >> 2;
    const int m0 = blockIdx.x * 128;
    const int y  = blockIdx.y;
    const uint32_t sb = smem_u32(sm);

    const __nv_bfloat16 *Bh, *Bl;
    const float* bias;
    int stride;
    float* outp;
    if (y == 0)      { Bh = wlat_h;      Bl = wlat_l;      bias = b_lat;      stride = 128; outp = out; }
    else if (y == 1) { Bh = wlat_h + 64; Bl = wlat_l + 64; bias = b_lat + 64; stride = 128; outp = out + OUT_S_OFF; }
    else             { Bh = winit_h;     Bl = winit_l;     bias = b_init;     stride = 64;  outp = out + OUT_Z_OFF; }

    float acc[2][4][4];
    #pragma unroll
    for (int j=0;j<4;j++)
        #pragma unroll
        for (int q=0;q<4;q++){ acc[0][j][q]=0.0f; acc[1][j][q]=0.0f; }

    for (int c = 0; c < 4; c++) {
        const int c64 = c * 64;
        if (c) __syncthreads();
        #pragma unroll
        for (int it = 0; it < 4; it++) {
            int g = tid + it*256;
            int row = g >> 3, gg = g & 7;
            uint32_t off = (uint32_t)(row*128 + gg*16); off ^= (off>>3)&0x70;
            size_t src = (size_t)(m0+row)*K + c64 + gg*8;
            *(uint4*)(sm + AHo + off) = *(const uint4*)(Ah_g + src);
            *(uint4*)(sm + ALo + off) = *(const uint4*)(Al_g + src);
        }
        #pragma unroll
        for (int it = 0; it < 2; it++) {
            int g = tid + it*256;
            int row = g >> 3, gg = g & 7;
            uint32_t off = (uint32_t)(row*128 + gg*16); off ^= (off>>3)&0x70;
            size_t src = (size_t)(c64+row)*stride + gg*8;
            *(uint4*)(sm + BHo + off) = *(const uint4*)(Bh + src);
            *(uint4*)(sm + BLo + off) = *(const uint4*)(Bl + src);
        }
        __syncthreads();
        mma_block<2>(acc, sb+AHo, sb+ALo, sb+BHo, sb+BLo, wm, wn*32, lid);
    }

    #pragma unroll
    for (int nt = 0; nt < 4; nt++) {
        const int n = wn*32 + nt*8 + (lid&3)*2;
        float2 bb = *(const float2*)(bias + n);
        #pragma unroll
        for (int mt = 0; mt < 2; mt++) {
            #pragma unroll
            for (int half = 0; half < 2; half++) {
                const int m = m0 + wm*32 + mt*16 + (lid>>2) + half*8;
                float v0 = acc[mt][nt][half*2+0] + bb.x;
                float v1 = acc[mt][nt][half*2+1] + bb.y;
                if (y == 1) { v0 = __expf(0.5f*v0); v1 = __expf(0.5f*v1); }
                *(float2*)(outp + (size_t)m*64 + n) = make_float2(v0, v1);
            }
        }
    }
}

// ---------------------------------------------------------------------------
// dg1_k: only used ONCE (k=0) to produce h1 from z0.
// ---------------------------------------------------------------------------
__global__ void __launch_bounds__(256,2) dg1_k(
    const float* __restrict__ Zsrc,
    const __nv_bfloat16* __restrict__ Bh_g, const __nv_bfloat16* __restrict__ Bl_g,
    const float* __restrict__ bias512, const float* __restrict__ w0512,
    const float* __restrict__ ts, int kstep,
    __nv_bfloat162* __restrict__ outDh, __nv_bfloat162* __restrict__ outDl,
    __nv_bfloat162* __restrict__ outGh, __nv_bfloat162* __restrict__ outGl)
{
    constexpr int NG = 512;
    constexpr int AHo=0, ALo=16384, BHo=32768, BLo=49152;
    extern __shared__ char sm[];
    const int tid=threadIdx.x, lid=tid&31, wid=tid>>5;
    const int wm=wid&3, wn=wid>>2;
    const int m0 = blockIdx.x*128;
    const int n0c = blockIdx.y*128;
    const uint32_t sb = smem_u32(sm);

    float acc[2][8][4];
    #pragma unroll
    for (int i=0;i<2;i++)
        #pragma unroll
        for (int j=0;j<8;j++)
            #pragma unroll
            for (int q=0;q<4;q++) acc[i][j][q]=0.0f;

    #pragma unroll
    for (int it = 0; it < 4; it++) {
        int g = tid + it*256;
        int row = g >> 4, gg = g & 15;
        int sbt = gg >> 3, gin = gg & 7;
        uint32_t off = (uint32_t)(row*128 + gin*16);
        off ^= (off >> 3) & 0x70;
        off += (uint32_t)sbt * 8192;
        size_t src = (size_t)row*NG + n0c + gg*8;
        cpa16(sb + BHo + off, Bh_g + src);
        cpa16(sb + BLo + off, Bl_g + src);
    }
    CP_COMMIT();

    #pragma unroll
    for (int it = 0; it < 4; it++) {
        int g = tid + it*256;
        int row = g >> 3, gg = g & 7;
        uint32_t off = (uint32_t)(row*128 + gg*16);
        off ^= (off >> 3) & 0x70;
        const float* zp = Zsrc + (size_t)(m0+row)*64 + gg*8;
        float4 f0 = *(const float4*)zp;
        float4 f1 = *(const float4*)(zp+4);
        float fv[8] = {f0.x,f0.y,f0.z,f0.w,f1.x,f1.y,f1.z,f1.w};
        alignas(16) __nv_bfloat16 hv[8], lv[8];
        #pragma unroll
        for (int j=0;j<8;j++){
            __nv_bfloat16 h = __float2bfloat16(fv[j]);
            hv[j]=h; lv[j]=__float2bfloat16(fv[j]-__bfloat162float(h));
        }
        *(uint4*)(sm + AHo + off) = *(const uint4*)hv;
        *(uint4*)(sm + ALo + off) = *(const uint4*)lv;
    }
    CP_WAIT(0);
    __syncthreads();

    mma_block<4>(acc, sb+AHo, sb+ALo, sb+BHo, sb+BLo, wm, wn*64, lid);

    const bool isg = (n0c >= 256);
    __nv_bfloat162* oh = isg ? outGh : outDh;
    __nv_bfloat162* ol = isg ? outGl : outDl;
    const int nsub = isg ? 256 : 0;
    const float tval = __ldg(&ts[kstep]);

    #pragma unroll
    for (int nt = 0; nt < 8; nt++) {
        const int n = n0c + wn*64 + nt*8 + (lid&3)*2;
        float2 bb = *(const float2*)(bias512 + n);
        float2 w0 = *(const float2*)(w0512 + n);
        float b0 = fmaf(tval, w0.x, bb.x);
        float b1 = fmaf(tval, w0.y, bb.y);
        #pragma unroll
        for (int mt = 0; mt < 2; mt++) {
            #pragma unroll
            for (int half = 0; half < 2; half++) {
                const int m = m0 + wm*32 + mt*16 + (lid>>2) + half*8;
                float v0 = f_swish(acc[mt][nt][half*2+0] + b0);
                float v1 = f_swish(acc[mt][nt][half*2+1] + b1);
                __nv_bfloat16 h0 = __float2bfloat16(v0);
                __nv_bfloat16 h1 = __float2bfloat16(v1);
                __nv_bfloat16 l0 = __float2bfloat16(v0 - __bfloat162float(h0));
                __nv_bfloat16 l1 = __float2bfloat16(v1 - __bfloat162float(h1));
                size_t pidx = ((size_t)m*256 + (n - nsub)) >> 1;
                __nv_bfloat162 hp; hp.x = h0; hp.y = h1;
                __nv_bfloat162 lp; lp.x = l0; lp.y = l1;
                oh[pidx] = hp;
                ol[pidx] = lp;
            }
        }
    }
}

// ---------------------------------------------------------------------------
// SCAN step kernel (512 threads): d2 -> d3 -> g2 -> Euler -> h1(k+1).
// ---------------------------------------------------------------------------
__global__ void __launch_bounds__(512,1) d23g2_k(
    const __nv_bfloat16* __restrict__ Ah_g, const __nv_bfloat16* __restrict__ Al_g,
    const __nv_bfloat16* __restrict__ Wd2h, const __nv_bfloat16* __restrict__ Wd2l,
    const float* __restrict__ bd2,
    const __nv_bfloat16* __restrict__ Gh, const __nv_bfloat16* __restrict__ Gl,
    const __nv_bfloat16* __restrict__ Wd3h, const __nv_bfloat16* __restrict__ Wd3l,
    const float* __restrict__ bd3,
    const __nv_bfloat16* __restrict__ Wg2h, const __nv_bfloat16* __restrict__ Wg2l,
    const float* __restrict__ bg2,
    const float* __restrict__ Zsrc, const float* __restrict__ ts, int kstep,
    const float* __restrict__ noise, float* __restrict__ zout,
    const __nv_bfloat16* __restrict__ wdgh, const __nv_bfloat16* __restrict__ wdgl,
    const float* __restrict__ bdg, const float* __restrict__ w0dg,
    int do_h1,
    __nv_bfloat162* __restrict__ outDh, __nv_bfloat162* __restrict__ outDl,
    __nv_bfloat162* __restrict__ outGh, __nv_bfloat162* __restrict__ outGl)
{
    extern __shared__ char sm[];
    const int tid=threadIdx.x, lid=tid&31, wid=tid>>5;
    const int wm=wid&3, wn=wid>>2;
    const int m0 = blockIdx.x*128;
    const uint32_t sb = smem_u32(sm);

    auto load_Wd3 = [&](int c, int s){
        const uint32_t stb = sb + 196608u + (uint32_t)s*16384u;
        int row = tid>>3, gg = tid&7;
        uint32_t off = (uint32_t)(row*128 + gg*16); off ^= (off>>3)&0x70;
        size_t src = (size_t)(c*64+row)*64 + gg*8;
        cpa16(stb + 0    + off, Wd3h + src);
        cpa16(stb + 8192 + off, Wd3l + src);
        CP_COMMIT();
    };

    auto load_g2 = [&](int c, int s){
        const uint32_t stb = sb + 131072u + (uint32_t)s*49152u;
        const int c64 = c*64;
        #pragma unroll
        for (int it=0; it<2; it++){
            int g = tid + it*512;
            int row = g>>3, gg = g&7;
            uint32_t off = (uint32_t)(row*128 + gg*16); off ^= (off>>3)&0x70;
            size_t src = (size_t)(m0+row)*256 + c64 + gg*8;
            cpa16(stb + 0     + off, Gh + src);
            cpa16(stb + 16384 + off, Gl + src);
        }
        {
            int row = tid>>3, gg = tid&7;
            uint32_t off = (uint32_t)(row*128 + gg*16); off ^= (off>>3)&0x70;
            size_t src = (size_t)(c64+row)*64 + gg*8;
            cpa16(stb + 32768 + off, Wg2h + src);
            cpa16(stb + 40960 + off, Wg2l + src);
        }
        CP_COMMIT();
    };

    auto load_Wdg = [&](){
        #pragma unroll
        for (int it=0; it<8; it++){
            int g = tid + it*512;
            int row = g>>6, gg = g&63;
            int sbt = gg>>3, gin = gg&7;
            uint32_t off = (uint32_t)(row*128 + gin*16); off ^= (off>>3)&0x70;
            off += (uint32_t)sbt*8192;
            size_t src = (size_t)row*512 + gg*8;
            cpa16(sb + 32768 + off, wdgh + src);
            cpa16(sb + 98304 + off, wdgl + src);
        }
        CP_COMMIT();
    };

    // ======== phase 1: d2 ========
    {
        constexpr int SST = 98304;
        constexpr int AHo=0, ALo=16384, BHo=32768, BLo=65536;

        float acc[2][8][4];
        #pragma unroll
        for (int i=0;i<2;i++)
            #pragma unroll
            for (int j=0;j<8;j++)
                #pragma unroll
                for (int q=0;q<4;q++) acc[i][j][q]=0.0f;

        auto load_chunk = [&](int c, int s){
            const uint32_t stb = sb + (uint32_t)s*SST;
            const int c64 = c*64;
            #pragma unroll
            for (int it=0; it<2; it++){
                int g = tid + it*512;
                int row = g>>3, gg = g&7;
                uint32_t off = (uint32_t)(row*128 + gg*16); off ^= (off>>3)&0x70;
                size_t src = (size_t)(m0+row)*256 + c64 + gg*8;
                cpa16(stb + AHo + off, Ah_g + src);
                cpa16(stb + ALo + off, Al_g + src);
            }
            #pragma unroll
            for (int it=0; it<4; it++){
                int g = tid + it*512;
                int row = g>>5, gg = g&31;
                int sbt = gg>>3, gin = gg&7;
                uint32_t off = (uint32_t)(row*128 + gin*16); off ^= (off>>3)&0x70;
                off += (uint32_t)sbt*8192;
                size_t src = (size_t)(c64+row)*256 + gg*8;
                cpa16(stb + BHo + off, Wd2h + src);
                cpa16(stb + BLo + off, Wd2l + src);
            }
            CP_COMMIT();
        };

        load_chunk(0, 0);
        load_Wd3(0, 0);
        for (int c = 0; c < 4; c++) {
            if (c+1 < 4) { load_chunk(c+1, (c+1)&1); CP_WAIT(1); }
            else         { CP_WAIT(0); }
            __syncthreads();
            const uint32_t stb = sb + (uint32_t)(c&1)*SST;
            mma_block<4>(acc, stb+AHo, stb+ALo, stb+BHo, stb+BLo, wm, wn*64, lid);
            __syncthreads();
        }

        #pragma unroll
        for (int nt = 0; nt < 8; nt++) {
            const int n = wn*64 + nt*8 + (lid&3)*2;
            float2 bb = *(const float2*)(bd2 + n);
            const int ck = n >> 6;
            #pragma unroll
            for (int mt = 0; mt < 2; mt++) {
                #pragma unroll
                for (int half = 0; half < 2; half++) {
                    const int r = wm*32 + mt*16 + (lid>>2) + half*8;
                    float v0 = f_swish(acc[mt][nt][half*2+0] + bb.x);
                    float v1 = f_swish(acc[mt][nt][half*2+1] + bb.y);
                    __nv_bfloat16 h0 = __float2bfloat16(v0);
                    __nv_bfloat16 h1 = __float2bfloat16(v1);
                    __nv_bfloat16 l0 = __float2bfloat16(v0 - __bfloat162float(h0));
                    __nv_bfloat16 l1 = __float2bfloat16(v1 - __bfloat162float(h1));
                    uint32_t off = (uint32_t)(r*128 + (n&63)*2); off ^= (off>>3)&0x70;
                    __nv_bfloat162 hp; hp.x=h0; hp.y=h1;
                    __nv_bfloat162 lp; lp.x=l0; lp.y=l1;
                    *(__nv_bfloat162*)(sm + ck*16384 + off) = hp;
                    *(__nv_bfloat162*)(sm + 65536 + ck*16384 + off) = lp;
                }
            }
        }
        __syncthreads();
    }

    // ======== phase 2: d3 ========
    float accD[2][2][4];
    #pragma unroll
    for (int j=0;j<2;j++)
        #pragma unroll
        for (int q=0;q<4;q++){ accD[0][j][q]=0.0f; accD[1][j][q]=0.0f; }
    {
        load_g2(0, 0);
        for (int c = 0; c < 4; c++) {
            if (c+1 < 4) { load_Wd3(c+1, (c+1)&1); CP_WAIT(1); }
            else         { CP_WAIT(0); }
            __syncthreads();
            const uint32_t wstb = sb + 196608u + (uint32_t)(c&1)*16384u;
            mma_block<1>(accD, sb + (uint32_t)c*16384u, sb + 65536u + (uint32_t)c*16384u,
                         wstb, wstb + 8192u, wm, wn*16, lid);
            __syncthreads();
        }
    }

    // ======== phase 3: g2 (Wdg prefetch on the last chunk) ========
    float accG[2][2][4];
    #pragma unroll
    for (int j=0;j<2;j++)
        #pragma unroll
        for (int q=0;q<4;q++){ accG[0][j][q]=0.0f; accG[1][j][q]=0.0f; }
    {
        for (int c = 0; c < 4; c++) {
            if (c+1 < 4) { load_g2(c+1, (c+1)&1); CP_WAIT(1); }
            else {
                if (do_h1) { load_Wdg(); CP_WAIT(1); }
                else       { CP_WAIT(0); }
            }
            __syncthreads();
            const uint32_t stb = sb + 131072u + (uint32_t)(c&1)*49152u;
            mma_block<1>(accG, stb, stb+16384u, stb+32768u, stb+40960u, wm, wn*16, lid);
            __syncthreads();
        }
    }

    // ======== phase 4: Euler-Maruyama update (+ z_new split to smem) ========
    const float t0 = __ldg(&ts[kstep]);
    const float t1 = __ldg(&ts[kstep+1]);
    const float dt = t1 - t0;
    const float sq = sqrtf(dt);
    const float* noise_k = noise + (size_t)kstep*ZSLICE;

    #pragma unroll
    for (int nt = 0; nt < 2; nt++) {
        const int n = wn*16 + nt*8 + (lid&3)*2;
        float2 bd = *(const float2*)(bd3 + n);
        float2 bg = *(const float2*)(bg2 + n);
        #pragma unroll
        for (int mt = 0; mt < 2; mt++) {
            #pragma unroll
            for (int half = 0; half < 2; half++) {
                const int r = wm*32 + mt*16 + (lid>>2) + half*8;
                const int m = m0 + r;
                float d0 = accD[mt][nt][half*2+0] + bd.x;
                float d1 = accD[mt][nt][half*2+1] + bd.y;
                float g0 = f_softplus(accG[mt][nt][half*2+0] + bg.x);
                float g1 = f_softplus(accG[mt][nt][half*2+1] + bg.y);
                size_t idx = (size_t)m*64 + n;
                float2 zz = *(const float2*)(Zsrc + idx);
                float2 nn = *(const float2*)(noise_k + idx);
                float z0 = zz.x + d0*dt + g0*sq*nn.x;
                float z1 = zz.y + d1*dt + g1*sq*nn.y;
                *(float2*)(zout + idx) = make_float2(z0, z1);
                if (do_h1) {
                    __nv_bfloat16 h0 = __float2bfloat16(z0);
                    __nv_bfloat16 h1 = __float2bfloat16(z1);
                    __nv_bfloat16 l0 = __float2bfloat16(z0 - __bfloat162float(h0));
                    __nv_bfloat16 l1 = __float2bfloat16(z1 - __bfloat162float(h1));
                    uint32_t off = (uint32_t)(r*128 + n*2); off ^= (off>>3)&0x70;
                    __nv_bfloat162 hp; hp.x=h0; hp.y=h1;
                    __nv_bfloat162 lp; lp.x=l0; lp.y=l1;
                    *(__nv_bfloat162*)(sm + off) = hp;
                    *(__nv_bfloat162*)(sm + 16384 + off) = lp;
                }
            }
        }
    }

    // ======== phase 5: h1(k+1) = swish([t1, z_new] @ [Wd1|Wg1]) ========
    if (do_h1) {
        CP_WAIT(0);
        __syncthreads();
        #pragma unroll
        for (int hb = 0; hb < 2; hb++) {
            float acc5[2][8][4];
            #pragma unroll
            for (int j=0;j<8;j++)
                #pragma unroll
                for (int q=0;q<4;q++){ acc5[0][j][q]=0.0f; acc5[1][j][q]=0.0f; }

            mma_block<4>(acc5, sb, sb+16384u,
                         sb+32768u + (uint32_t)hb*32768u,
                         sb+98304u + (uint32_t)hb*32768u, wm, wn*64, lid);

            __nv_bfloat162* oh = hb ? outGh : outDh;
            __nv_bfloat162* ol = hb ? outGl : outDl;
            #pragma unroll
            for (int nt = 0; nt < 8; nt++) {
                const int nl = wn*64 + nt*8 + (lid&3)*2;
                const int ng = hb*256 + nl;
                float2 bb = *(const float2*)(bdg + ng);
                float2 w0 = *(const float2*)(w0dg + ng);
                float b0 = fmaf(t1, w0.x, bb.x);
                float b1 = fmaf(t1, w0.y, bb.y);
                #pragma unroll
                for (int mt = 0; mt < 2; mt++) {
                    #pragma unroll
                    for (int half = 0; half < 2; half++) {
                        const int m = m0 + wm*32 + mt*16 + (lid>>2) + half*8;
                        float v0 = f_swish(acc5[mt][nt][half*2+0] + b0);
                        float v1 = f_swish(acc5[mt][nt][half*2+1] + b1);
                        __nv_bfloat16 h0 = __float2bfloat16(v0);
                        __nv_bfloat16 h1 = __float2bfloat16(v1);
                        __nv_bfloat16 l0 = __float2bfloat16(v0 - __bfloat162float(h0));
                        __nv_bfloat16 l1 = __float2bfloat16(v1 - __bfloat162float(h1));
                        size_t pidx = ((size_t)m*256 + nl) >> 1;
                        __nv_bfloat162 hp; hp.x=h0; hp.y=h1;
                        __nv_bfloat162 lp; lp.x=l0; lp.y=l1;
                        oh[pidx] = hp;
                        ol[pidx] = lp;
                    }
                }
            }
        }
    }
}

// ---------------- prep: ALL elementwise splits in ONE kernel ----------------
#define PREP_TOTAL (4194304 + 671744)
__global__ void prep_all(
    const float* __restrict__ x,
    const float* __restrict__ W_in, const float* __restrict__ Wb1,
    const float* __restrict__ Wb2,  const float* __restrict__ W_fo,
    const float* __restrict__ W_lat,const float* __restrict__ W_init,
    const float* __restrict__ Wd2,  const float* __restrict__ Wd3,
    const float* __restrict__ Wg2,
    __nv_bfloat16* __restrict__ xh, __nv_bfloat16* __restrict__ xl,
    __nv_bfloat16* __restrict__ wh, __nv_bfloat16* __restrict__ wl)
{
    int i = blockIdx.x * 256 + threadIdx.x;
    float v;
    __nv_bfloat16 *dh, *dl;
    if (i < 4194304) {
        v = x[i]; dh = xh + i; dl = xl + i;
    } else {
        int j = i - 4194304;
        const float* s; int base;
        if      (j < 65536)            { s = W_in;   base = OFF_WIN;   }
        else if ((j -= 65536) < 196608){ s = Wb1;    base = OFF_WB1;   }
        else if ((j -= 196608) < 196608){ s = Wb2;   base = OFF_WB2;   }
        else if ((j -= 196608) < 65536){ s = W_fo;   base = OFF_WFO;   }
        else if ((j -= 65536) < 32768) { s = W_lat;  base = OFF_WLAT;  }
        else if ((j -= 32768) < 16384) { s = W_init; base = OFF_WINIT; }
        else if ((j -= 16384) < 65536) { s = Wd2;    base = OFF_WD2;   }
        else if ((j -= 65536) < 16384) { s = Wd3;    base = OFF_WD3;   }
        else                           { j -= 16384; s = Wg2; base = OFF_WG2; }
        v = s[j]; dh = wh + base + j; dl = wl + base + j;
    }
    __nv_bfloat16 h = __float2bfloat16(v);
    *dh = h;
    *dl = __float2bfloat16(v - __bfloat162float(h));
}

__global__ void prep_dg1(const float* __restrict__ Wd1, const float* __restrict__ Wg1,
                         const float* __restrict__ bd1, const float* __restrict__ bg1,
                         __nv_bfloat16* __restrict__ wh, __nv_bfloat16* __restrict__ wl,
                         float* __restrict__ bias, float* __restrict__ w0)
{
    int idx = blockIdx.x * 256 + threadIdx.x;   // 64*512
    int k = idx >> 9, n = idx & 511;
    float v = (n < 256) ? Wd1[(size_t)(k+1)*256 + n] : Wg1[(size_t)(k+1)*256 + (n-256)];
    __nv_bfloat16 h = __float2bfloat16(v);
    wh[idx] = h;
    wl[idx] = __float2bfloat16(v - __bfloat162float(h));
    if (idx < 512) {
        bias[idx] = (idx < 256) ? bd1[idx] : bg1[idx-256];
        w0[idx]   = (idx < 256) ? Wd1[idx] : Wg1[idx-256];
    }
}

// ---------------------------------------------------------------------------
extern "C" void kernel_launch(void* const* d_in, const int* in_sizes, int n_in,
                              void* d_out, int out_size)
{
    const float* x     = (const float*)d_in[0];
    const float* ts    = (const float*)d_in[1];
    const float* noise = (const float*)d_in[2];
    const float* W_in  = (const float*)d_in[3];
    const float* b_in  = (const float*)d_in[4];
    const float* Wb1   = (const float*)d_in[5];
    const float* bb1   = (const float*)d_in[6];
    const float* Wb2   = (const float*)d_in[7];
    const float* bb2   = (const float*)d_in[8];
    const float* W_fo  = (const float*)d_in[9];
    const float* b_fo  = (const float*)d_in[10];
    const float* W_lat = (const float*)d_in[11];
    const float* b_lat = (const float*)d_in[12];
    const float* W_init= (const float*)d_in[13];
    const float* b_init= (const float*)d_in[14];
    const float* Wd1   = (const float*)d_in[15];
    const float* bd1   = (const float*)d_in[16];
    const float* Wd2   = (const float*)d_in[17];
    const float* bd2   = (const float*)d_in[18];
    const float* Wd3   = (const float*)d_in[19];
    const float* bd3   = (const float*)d_in[20];
    const float* Wg1   = (const float*)d_in[21];
    const float* bg1   = (const float*)d_in[22];
    const float* Wg2   = (const float*)d_in[23];
    const float* bg2   = (const float*)d_in[24];
    float* out = (float*)d_out;

    __nv_bfloat16 *xh, *xl, *ah, *al, *bh, *bl, *gh, *gl, *wh, *wl, *wdgh, *wdgl;
    float *hres, *bdg, *w0dg;
    cudaGetSymbolAddress((void**)&xh,  g_xh);
    cudaGetSymbolAddress((void**)&xl,  g_xl);
    cudaGetSymbolAddress((void**)&ah,  g_ah);
    cudaGetSymbolAddress((void**)&al,  g_al);
    cudaGetSymbolAddress((void**)&bh,  g_bh);
    cudaGetSymbolAddress((void**)&bl,  g_bl);
    cudaGetSymbolAddress((void**)&gh,  g_gh);
    cudaGetSymbolAddress((void**)&gl,  g_gl);
    cudaGetSymbolAddress((void**)&wh,  g_wh);
    cudaGetSymbolAddress((void**)&wl,  g_wl);
    cudaGetSymbolAddress((void**)&wdgh,g_wdgh);
    cudaGetSymbolAddress((void**)&wdgl,g_wdgl);
    cudaGetSymbolAddress((void**)&hres,g_hres);
    cudaGetSymbolAddress((void**)&bdg, g_bdg);
    cudaGetSymbolAddress((void**)&w0dg,g_w0dg);

    // ---- prep: 2 launches total ----
    prep_all<<<PREP_TOTAL/256, 256>>>(x, W_in, Wb1, Wb2, W_fo, W_lat, W_init,
                                      Wd2, Wd3, Wg2, xh, xl, wh, wl);
    prep_dg1<<<128, 256>>>(Wd1, Wg1, bd1, bg1, wdgh, wdgl, bdg, w0dg);

    // ---- encoder kernel handles ----
    auto* kIN  = mgemm<256,256,ACT_SWISH, false,true, true >;
    auto* kFO  = mgemm<256,256,ACT_NONE,  false,true, false>;

    const int SM128 = 32768 + 2*128*128;   // 65536
    const int SM64  = 32768 + 2*64*128;    // 49152
    cudaFuncSetAttribute((const void*)kIN,  cudaFuncAttributeMaxDynamicSharedMemorySize, SM128);
    cudaFuncSetAttribute((const void*)kFO,  cudaFuncAttributeMaxDynamicSharedMemorySize, SM128);
    cudaFuncSetAttribute((const void*)blk_k,   cudaFuncAttributeMaxDynamicSharedMemorySize, 196608);
    cudaFuncSetAttribute((const void*)tail_k,  cudaFuncAttributeMaxDynamicSharedMemorySize, SM64);
    cudaFuncSetAttribute((const void*)dg1_k,   cudaFuncAttributeMaxDynamicSharedMemorySize, 65536);
    cudaFuncSetAttribute((const void*)d23g2_k, cudaFuncAttributeMaxDynamicSharedMemorySize, 229376);

    dim3 blk(256);
    dim3 gN256(BATCH/128, 2);

    __nv_bfloat162 *ah2 = (__nv_bfloat162*)ah, *al2 = (__nv_bfloat162*)al;
    __nv_bfloat162 *bh2 = (__nv_bfloat162*)bh, *bl2 = (__nv_bfloat162*)bl;
    __nv_bfloat162 *gh2 = (__nv_bfloat162*)gh, *gl2 = (__nv_bfloat162*)gl;

    // ---- encoder ----
    kIN<<<gN256, blk, SM128>>>(xh, xl, wh+OFF_WIN, wl+OFF_WIN, b_in,
                               nullptr, hres, ah2, al2);
    for (int i = 0; i < 3; i++) {
        blk_k<<<dim3(BATCH/128), dim3(512), 196608>>>(
            ah, al,
            wh+OFF_WB1+i*65536, wl+OFF_WB1+i*65536, bb1 + i*HID,
            wh+OFF_WB2+i*65536, wl+OFF_WB2+i*65536, bb2 + i*HID,
            hres, ah2, al2);
    }
    kFO<<<gN256, blk, SM128>>>(ah, al, wh+OFF_WFO, wl+OFF_WFO, b_fo,
                               nullptr, nullptr, bh2, bl2);
    tail_k<<<dim3(BATCH/128, 3), blk, SM64>>>(bh, bl,
                                              wh+OFF_WLAT, wl+OFF_WLAT, b_lat,
                                              wh+OFF_WINIT, wl+OFF_WINIT, b_init,
                                              out);

    // ---- SDE scan: dg1 once for z0, then 1 kernel/step ----
    dg1_k<<<dim3(BATCH/128, 4), blk, 65536>>>(out + OUT_Z_OFF, wdgh, wdgl, bdg, w0dg,
                                              ts, 0, ah2, al2, gh2, gl2);
    for (int k = 0; k < NSTEP; k++) {
        const float* z = out + OUT_Z_OFF + (size_t)k * ZSLICE;
        float* zn = out + OUT_Z_OFF + (size_t)(k+1) * ZSLICE;
        d23g2_k<<<dim3(BATCH/128, 1), dim3(512), 229376>>>(
            ah, al, wh+OFF_WD2, wl+OFF_WD2, bd2,
            gh, gl, wh+OFF_WD3, wl+OFF_WD3, bd3,
            wh+OFF_WG2, wl+OFF_WG2, bg2,
            z, ts, k, noise, zn,
            wdgh, wdgl, bdg, w0dg, (k+1 < NSTEP) ? 1 : 0,
            ah2, al2, gh2, gl2);
    }
}

// round 17
// speedup vs baseline: 1.0225x; 1.0149x over previous
#include <cuda_runtime.h>
#include <cuda_bf16.h>
#include <stdint.h>
#include <math.h>

#define BATCH 16384
#define HID   256
#define LATD  64
#define NSTEP 63

#define OUT_S_OFF  (BATCH*LATD)
#define OUT_Z_OFF  (2*BATCH*LATD)
#define ZSLICE     (BATCH*LATD)

// ---------------- scratch (static device arrays; no allocation) ----------------
__device__ __nv_bfloat16 g_xh[BATCH*HID], g_xl[BATCH*HID];
__device__ __nv_bfloat16 g_ah[BATCH*HID], g_al[BATCH*HID];
__device__ __nv_bfloat16 g_bh[BATCH*HID], g_bl[BATCH*HID];
__device__ __nv_bfloat16 g_gh[BATCH*HID], g_gl[BATCH*HID];
__device__ float g_hres[BATCH*HID];

// combined [Wd1|Wg1] weights: [64][512]
__device__ __nv_bfloat16 g_wdgh[64*512], g_wdgl[64*512];
__device__ float g_bdg[512], g_w0dg[512];

// weight scratch: elementwise hi/lo split, natural [K][N] layout
#define OFF_WIN   0
#define OFF_WB1   65536
#define OFF_WB2   (OFF_WB1 + 3*65536)
#define OFF_WFO   (OFF_WB2 + 3*65536)
#define OFF_WLAT  (OFF_WFO + 65536)
#define OFF_WINIT (OFF_WLAT + 32768)
#define OFF_WD2   (OFF_WINIT + 16384)
#define OFF_WD3   (OFF_WD2 + 65536)
#define OFF_WG2   (OFF_WD3 + 16384)
#define WT_TOTAL  (OFF_WG2 + 16384)

__device__ __nv_bfloat16 g_wh[WT_TOTAL];
__device__ __nv_bfloat16 g_wl[WT_TOTAL];

enum { ACT_NONE=0, ACT_SWISH=1, ACT_SOFTPLUS=2 };

__device__ __forceinline__ float f_swish(float v){
    return v * (1.0f / (1.0f + __expf(-v)));
}
__device__ __forceinline__ float f_softplus(float v){
    return fmaxf(v, 0.0f) + log1pf(__expf(-fabsf(v)));
}

__device__ __forceinline__ uint32_t smem_u32(const void* p){
    uint32_t a;
    asm("{ .reg .u64 t; cvta.to.shared.u64 t, %1; cvt.u32.u64 %0, t; }" : "=r"(a) : "l"(p));
    return a;
}
__device__ __forceinline__ void ldsm4(uint32_t (&r)[4], uint32_t addr){
    asm volatile("ldmatrix.sync.aligned.m8n8.x4.shared.b16 {%0,%1,%2,%3}, [%4];"
        : "=r"(r[0]),"=r"(r[1]),"=r"(r[2]),"=r"(r[3]) : "r"(addr));
}
__device__ __forceinline__ void ldsm4t(uint32_t (&r)[4], uint32_t addr){
    asm volatile("ldmatrix.sync.aligned.m8n8.x4.trans.shared.b16 {%0,%1,%2,%3}, [%4];"
        : "=r"(r[0]),"=r"(r[1]),"=r"(r[2]),"=r"(r[3]) : "r"(addr));
}
__device__ __forceinline__ void mma_bf16(float (&d)[4], const uint32_t (&a)[4],
                                         uint32_t b0, uint32_t b1){
    asm volatile(
        "mma.sync.aligned.m16n8k16.row.col.f32.bf16.bf16.f32 "
        "{%0,%1,%2,%3}, {%4,%5,%6,%7}, {%8,%9}, {%0,%1,%2,%3};"
        : "+f"(d[0]),"+f"(d[1]),"+f"(d[2]),"+f"(d[3])
        : "r"(a[0]),"r"(a[1]),"r"(a[2]),"r"(a[3]), "r"(b0),"r"(b1));
}
__device__ __forceinline__ void cpa16(uint32_t dst, const void* src){
    asm volatile("cp.async.cg.shared.global [%0], [%1], 16;" :: "r"(dst), "l"(src));
}
#define CP_COMMIT() asm volatile("cp.async.commit_group;" ::: "memory")
#define CP_WAIT(n)  asm volatile("cp.async.wait_group %0;" :: "n"(n) : "memory")

// ---------------------------------------------------------------------------
// Single-pass 3-product MMA block (Ah*Bh + Al*Bh + Ah*Bl).
// ---------------------------------------------------------------------------
template<int NP>
__device__ __forceinline__ void mma_block(
    float (&acc)[2][NP*2][4],
    uint32_t AHb, uint32_t ALb, uint32_t BHb, uint32_t BLb,
    int wm, int wnbase, int lid)
{
    #pragma unroll
    for (int kk = 0; kk < 4; kk++) {
        uint32_t a0h[4], a1h[4], a0l[4], a1l[4];
        {
            int row = wm*32 + (lid&7) + ((lid>>3)&1)*8;
            int gg  = kk*2 + (lid>>4);
            uint32_t off = (uint32_t)(row*128 + gg*16); off ^= (off>>3)&0x70;
            ldsm4(a0h, AHb + off);
            ldsm4(a0l, ALb + off);
            uint32_t off2 = (uint32_t)((row+16)*128 + gg*16); off2 ^= (off2>>3)&0x70;
            ldsm4(a1h, AHb + off2);
            ldsm4(a1l, ALb + off2);
        }
        const int krow = kk*16 + (lid&7) + ((lid>>3)&1)*8;
        #pragma unroll
        for (int np = 0; np < NP; np++) {
            int colb = wnbase + np*16;
            int sbt  = colb >> 6;
            int gg   = ((colb & 63) >> 3) + (lid>>4);
            uint32_t off = (uint32_t)(krow*128 + gg*16); off ^= (off>>3)&0x70;
            off += (uint32_t)sbt * 8192;
            uint32_t b[4], bl[4];
            ldsm4t(b,  BHb + off);
            ldsm4t(bl, BLb + off);
            mma_bf16(acc[0][np*2  ], a0h, b[0], b[1]);
            mma_bf16(acc[1][np*2  ], a1h, b[0], b[1]);
            mma_bf16(acc[0][np*2+1], a0h, b[2], b[3]);
            mma_bf16(acc[1][np*2+1], a1h, b[2], b[3]);
            mma_bf16(acc[0][np*2  ], a0l, b[0], b[1]);
            mma_bf16(acc[1][np*2  ], a1l, b[0], b[1]);
            mma_bf16(acc[0][np*2+1], a0l, b[2], b[3]);
            mma_bf16(acc[1][np*2+1], a1l, b[2], b[3]);
            mma_bf16(acc[0][np*2  ], a0h, bl[0], bl[1]);
            mma_bf16(acc[1][np*2  ], a1h, bl[0], bl[1]);
            mma_bf16(acc[0][np*2+1], a0h, bl[2], bl[3]);
            mma_bf16(acc[1][np*2+1], a1h, bl[2], bl[3]);
        }
    }
}

// ---------------------------------------------------------------------------
// (encoder first/last) mma.sync bf16 split GEMM.
// ---------------------------------------------------------------------------
template<int K, int NG, int ACT, bool RES, bool WBF, bool WF32>
__global__ void __launch_bounds__(256,2) mgemm(
    const __nv_bfloat16* __restrict__ Ah_g, const __nv_bfloat16* __restrict__ Al_g,
    const __nv_bfloat16* __restrict__ Bh_g, const __nv_bfloat16* __restrict__ Bl_g,
    const float* __restrict__ bias,
    const float* __restrict__ resp,
    float* __restrict__ outF,
    __nv_bfloat162* __restrict__ outBh, __nv_bfloat162* __restrict__ outBl)
{
    constexpr int BN  = (NG >= 128) ? 128 : 64;
    constexpr int WN  = BN / 2;
    constexpr int NP  = WN / 16;
    constexpr int NCH = K / 64;
    constexpr int BSZ = BN * 128;
    constexpr int AHo = 0, ALo = 16384, BHo = 32768, BLo = 32768 + BSZ;

    extern __shared__ char sm[];
    const int tid = threadIdx.x;
    const int lid = tid & 31, wid = tid >> 5;
    const int wm  = wid & 3;
    const int wn  = wid >> 2;
    const int m0  = blockIdx.x * 128;
    const int n0c = blockIdx.y * BN;
    const uint32_t sb = smem_u32(sm);

    float acc[2][NP*2][4];
    #pragma unroll
    for (int i=0;i<2;i++)
        #pragma unroll
        for (int j=0;j<NP*2;j++)
            #pragma unroll
            for (int q=0;q<4;q++) acc[i][j][q] = 0.0f;

    for (int c = 0; c < NCH; c++) {
        const int c64 = c * 64;
        if (c) __syncthreads();

        #pragma unroll
        for (int it = 0; it < 4; it++) {
            int g = tid + it*256;
            int row = g >> 3, gg = g & 7;
            uint32_t off = (uint32_t)(row*128 + gg*16);
            off ^= (off >> 3) & 0x70;
            size_t src = (size_t)(m0+row)*K + c64 + gg*8;
            *(uint4*)(sm + AHo + off) = *(const uint4*)(Ah_g + src);
            *(uint4*)(sm + ALo + off) = *(const uint4*)(Al_g + src);
        }
        #pragma unroll
        for (int it = 0; it < BN/32; it++) {
            int g = tid + it*256;
            int row, gg;
            if (BN == 128) { row = g >> 4; gg = g & 15; }
            else           { row = g >> 3; gg = g & 7;  }
            int s = gg >> 3, gin = gg & 7;
            uint32_t off = (uint32_t)(row*128 + gin*16);
            off ^= (off >> 3) & 0x70;
            off += (uint32_t)s * 8192;
            size_t src = (size_t)(c64+row)*NG + n0c + gg*8;
            *(uint4*)(sm + BHo + off) = *(const uint4*)(Bh_g + src);
            *(uint4*)(sm + BLo + off) = *(const uint4*)(Bl_g + src);
        }
        __syncthreads();

        mma_block<NP>(acc, sb+AHo, sb+ALo, sb+BHo, sb+BLo, wm, wn*WN, lid);
    }

    #pragma unroll
    for (int nt = 0; nt < NP*2; nt++) {
        const int n = n0c + wn*WN + nt*8 + (lid&3)*2;
        float2 bb = *(const float2*)(bias + n);
        float b0 = bb.x, b1 = bb.y;
        #pragma unroll
        for (int mt = 0; mt < 2; mt++) {
            #pragma unroll
            for (int half = 0; half < 2; half++) {
                const int m = m0 + wm*32 + mt*16 + (lid>>2) + half*8;
                float v0 = acc[mt][nt][half*2+0] + b0;
                float v1 = acc[mt][nt][half*2+1] + b1;
                if (RES) {
                    float2 r2 = *(const float2*)(resp + (size_t)m*NG + n);
                    v0 += r2.x; v1 += r2.y;
                }
                if (ACT == ACT_SWISH)    { v0 = f_swish(v0);    v1 = f_swish(v1); }
                if (WF32)
                    *(float2*)(outF + (size_t)m*NG + n) = make_float2(v0, v1);
                if (WBF) {
                    __nv_bfloat16 h0 = __float2bfloat16(v0);
                    __nv_bfloat16 h1 = __float2bfloat16(v1);
                    __nv_bfloat16 l0 = __float2bfloat16(v0 - __bfloat162float(h0));
                    __nv_bfloat16 l1 = __float2bfloat16(v1 - __bfloat162float(h1));
                    size_t pidx = ((size_t)m*NG + n) >> 1;
                    __nv_bfloat162 hp; hp.x = h0; hp.y = h1;
                    __nv_bfloat162 lp; lp.x = l0; lp.y = l1;
                    outBh[pidx] = hp;
                    outBl[pidx] = lp;
                }
            }
        }
    }
}

// ---------------------------------------------------------------------------
// Fused residual block (512 threads) — unchanged from R16.
// ---------------------------------------------------------------------------
__global__ void __launch_bounds__(512,1) blk_k(
    const __nv_bfloat16* __restrict__ Ah_g, const __nv_bfloat16* __restrict__ Al_g,
    const __nv_bfloat16* __restrict__ W1h, const __nv_bfloat16* __restrict__ W1l,
    const float* __restrict__ b1,
    const __nv_bfloat16* __restrict__ W2h, const __nv_bfloat16* __restrict__ W2l,
    const float* __restrict__ b2,
    float* __restrict__ hres,
    __nv_bfloat162* __restrict__ outAh, __nv_bfloat162* __restrict__ outAl)
{
    extern __shared__ char sm[];
    const int tid=threadIdx.x, lid=tid&31, wid=tid>>5;
    const int wm=wid&3, wn=wid>>2;
    const int m0 = blockIdx.x*128;
    const uint32_t sb = smem_u32(sm);

    // ======== phase A: h1 = swish(h @ W1 + b1), 2-stage pipeline ========
    {
        constexpr int SST = 98304;
        constexpr int AHo=0, ALo=16384, BHo=32768, BLo=65536;

        float acc[2][8][4];
        #pragma unroll
        for (int j=0;j<8;j++)
            #pragma unroll
            for (int q=0;q<4;q++){ acc[0][j][q]=0.0f; acc[1][j][q]=0.0f; }

        auto load_chunk = [&](int c, int s){
            const uint32_t stb = sb + (uint32_t)s*SST;
            const int c64 = c*64;
            #pragma unroll
            for (int it=0; it<2; it++){
                int g = tid + it*512;
                int row = g>>3, gg = g&7;
                uint32_t off = (uint32_t)(row*128 + gg*16); off ^= (off>>3)&0x70;
                size_t src = (size_t)(m0+row)*256 + c64 + gg*8;
                cpa16(stb + AHo + off, Ah_g + src);
                cpa16(stb + ALo + off, Al_g + src);
            }
            #pragma unroll
            for (int it=0; it<4; it++){
                int g = tid + it*512;
                int row = g>>5, gg = g&31;
                int sbt = gg>>3, gin = gg&7;
                uint32_t off = (uint32_t)(row*128 + gin*16); off ^= (off>>3)&0x70;
                off += (uint32_t)sbt*8192;
                size_t src = (size_t)(c64+row)*256 + gg*8;
                cpa16(stb + BHo + off, W1h + src);
                cpa16(stb + BLo + off, W1l + src);
            }
            CP_COMMIT();
        };

        load_chunk(0, 0);
        for (int c = 0; c < 4; c++) {
            if (c+1 < 4) { load_chunk(c+1, (c+1)&1); CP_WAIT(1); }
            else         { CP_WAIT(0); }
            __syncthreads();
            const uint32_t stb = sb + (uint32_t)(c&1)*SST;
            mma_block<4>(acc, stb+AHo, stb+ALo, stb+BHo, stb+BLo, wm, wn*64, lid);
            __syncthreads();
        }

        // h1 -> SMEM bf16 split, A-chunk format
        #pragma unroll
        for (int nt = 0; nt < 8; nt++) {
            const int n = wn*64 + nt*8 + (lid&3)*2;
            float2 bb = *(const float2*)(b1 + n);
            const int ck = n >> 6;
            #pragma unroll
            for (int mt = 0; mt < 2; mt++) {
                #pragma unroll
                for (int half = 0; half < 2; half++) {
                    const int r = wm*32 + mt*16 + (lid>>2) + half*8;
                    float v0 = f_swish(acc[mt][nt][half*2+0] + bb.x);
                    float v1 = f_swish(acc[mt][nt][half*2+1] + bb.y);
                    __nv_bfloat16 h0 = __float2bfloat16(v0);
                    __nv_bfloat16 h1 = __float2bfloat16(v1);
                    __nv_bfloat16 l0 = __float2bfloat16(v0 - __bfloat162float(h0));
                    __nv_bfloat16 l1 = __float2bfloat16(v1 - __bfloat162float(h1));
                    uint32_t off = (uint32_t)(r*128 + (n&63)*2); off ^= (off>>3)&0x70;
                    __nv_bfloat162 hp; hp.x=h0; hp.y=h1;
                    __nv_bfloat162 lp; lp.x=l0; lp.y=l1;
                    *(__nv_bfloat162*)(sm + ck*16384 + off) = hp;
                    *(__nv_bfloat162*)(sm + 65536 + ck*16384 + off) = lp;
                }
            }
        }
        __syncthreads();
    }

    // ======== phase B: h_new = h1 @ W2 + b2 + hres ========
    float acc[2][8][4];
    #pragma unroll
    for (int j=0;j<8;j++)
        #pragma unroll
        for (int q=0;q<4;q++){ acc[0][j][q]=0.0f; acc[1][j][q]=0.0f; }

    for (int c = 0; c < 4; c++) {
        #pragma unroll
        for (int it=0; it<4; it++){
            int g = tid + it*512;
            int row = g>>5, gg = g&31;
            int sbt = gg>>3, gin = gg&7;
            uint32_t off = (uint32_t)(row*128 + gin*16); off ^= (off>>3)&0x70;
            off += (uint32_t)sbt*8192;
            size_t src = (size_t)(c*64+row)*256 + gg*8;
            cpa16(sb + 131072 + off, W2h + src);
            cpa16(sb + 163840 + off, W2l + src);
        }
        CP_COMMIT(); CP_WAIT(0);
        __syncthreads();
        mma_block<4>(acc, sb + (uint32_t)c*16384u, sb + 65536u + (uint32_t)c*16384u,
                     sb + 131072u, sb + 163840u, wm, wn*64, lid);
        __syncthreads();
    }

    #pragma unroll
    for (int nt = 0; nt < 8; nt++) {
        const int n = wn*64 + nt*8 + (lid&3)*2;
        float2 bb = *(const float2*)(b2 + n);
        #pragma unroll
        for (int mt = 0; mt < 2; mt++) {
            #pragma unroll
            for (int half = 0; half < 2; half++) {
                const int m = m0 + wm*32 + mt*16 + (lid>>2) + half*8;
                float2 r2 = *(const float2*)(hres + (size_t)m*256 + n);
                float v0 = acc[mt][nt][half*2+0] + bb.x + r2.x;
                float v1 = acc[mt][nt][half*2+1] + bb.y + r2.y;
                *(float2*)(hres + (size_t)m*256 + n) = make_float2(v0, v1);
                __nv_bfloat16 h0 = __float2bfloat16(v0);
                __nv_bfloat16 h1 = __float2bfloat16(v1);
                __nv_bfloat16 l0 = __float2bfloat16(v0 - __bfloat162float(h0));
                __nv_bfloat16 l1 = __float2bfloat16(v1 - __bfloat162float(h1));
                size_t pidx = ((size_t)m*256 + n) >> 1;
                __nv_bfloat162 hp; hp.x = h0; hp.y = h1;
                __nv_bfloat162 lp; lp.x = l0; lp.y = l1;
                outAh[pidx] = hp;
                outAl[pidx] = lp;
            }
        }
    }
}

// ---------------------------------------------------------------------------
// Encoder tail: one kernel for mu / s / z0.  grid (128, 3), BN=64.
// ---------------------------------------------------------------------------
__global__ void __launch_bounds__(256,2) tail_k(
    const __nv_bfloat16* __restrict__ Ah_g, const __nv_bfloat16* __restrict__ Al_g,
    const __nv_bfloat16* __restrict__ wlat_h, const __nv_bfloat16* __restrict__ wlat_l,
    const float* __restrict__ b_lat,
    const __nv_bfloat16* __restrict__ winit_h, const __nv_bfloat16* __restrict__ winit_l,
    const float* __restrict__ b_init,
    float* __restrict__ out)
{
    constexpr int K = 256;
    constexpr int AHo = 0, ALo = 16384, BHo = 32768, BLo = 32768 + 8192;
    extern __shared__ char sm[];
    const int tid = threadIdx.x, lid = tid & 31, wid = tid >> 5;
    const int wm = wid & 3, wn = wid >> 2;
    const int m0 = blockIdx.x * 128;
    const int y  = blockIdx.y;
    const uint32_t sb = smem_u32(sm);

    const __nv_bfloat16 *Bh, *Bl;
    const float* bias;
    int stride;
    float* outp;
    if (y == 0)      { Bh = wlat_h;      Bl = wlat_l;      bias = b_lat;      stride = 128; outp = out; }
    else if (y == 1) { Bh = wlat_h + 64; Bl = wlat_l + 64; bias = b_lat + 64; stride = 128; outp = out + OUT_S_OFF; }
    else             { Bh = winit_h;     Bl = winit_l;     bias = b_init;     stride = 64;  outp = out + OUT_Z_OFF; }

    float acc[2][4][4];
    #pragma unroll
    for (int j=0;j<4;j++)
        #pragma unroll
        for (int q=0;q<4;q++){ acc[0][j][q]=0.0f; acc[1][j][q]=0.0f; }

    for (int c = 0; c < 4; c++) {
        const int c64 = c * 64;
        if (c) __syncthreads();
        #pragma unroll
        for (int it = 0; it < 4; it++) {
            int g = tid + it*256;
            int row = g >> 3, gg = g & 7;
            uint32_t off = (uint32_t)(row*128 + gg*16); off ^= (off>>3)&0x70;
            size_t src = (size_t)(m0+row)*K + c64 + gg*8;
            *(uint4*)(sm + AHo + off) = *(const uint4*)(Ah_g + src);
            *(uint4*)(sm + ALo + off) = *(const uint4*)(Al_g + src);
        }
        #pragma unroll
        for (int it = 0; it < 2; it++) {
            int g = tid + it*256;
            int row = g >> 3, gg = g & 7;
            uint32_t off = (uint32_t)(row*128 + gg*16); off ^= (off>>3)&0x70;
            size_t src = (size_t)(c64+row)*stride + gg*8;
            *(uint4*)(sm + BHo + off) = *(const uint4*)(Bh + src);
            *(uint4*)(sm + BLo + off) = *(const uint4*)(Bl + src);
        }
        __syncthreads();
        mma_block<2>(acc, sb+AHo, sb+ALo, sb+BHo, sb+BLo, wm, wn*32, lid);
    }

    #pragma unroll
    for (int nt = 0; nt < 4; nt++) {
        const int n = wn*32 + nt*8 + (lid&3)*2;
        float2 bb = *(const float2*)(bias + n);
        #pragma unroll
        for (int mt = 0; mt < 2; mt++) {
            #pragma unroll
            for (int half = 0; half < 2; half++) {
                const int m = m0 + wm*32 + mt*16 + (lid>>2) + half*8;
                float v0 = acc[mt][nt][half*2+0] + bb.x;
                float v1 = acc[mt][nt][half*2+1] + bb.y;
                if (y == 1) { v0 = __expf(0.5f*v0); v1 = __expf(0.5f*v1); }
                *(float2*)(outp + (size_t)m*64 + n) = make_float2(v0, v1);
            }
        }
    }
}

// ---------------------------------------------------------------------------
// dg1_k: only used ONCE (k=0) to produce h1 from z0.
// ---------------------------------------------------------------------------
__global__ void __launch_bounds__(256,2) dg1_k(
    const float* __restrict__ Zsrc,
    const __nv_bfloat16* __restrict__ Bh_g, const __nv_bfloat16* __restrict__ Bl_g,
    const float* __restrict__ bias512, const float* __restrict__ w0512,
    const float* __restrict__ ts, int kstep,
    __nv_bfloat162* __restrict__ outDh, __nv_bfloat162* __restrict__ outDl,
    __nv_bfloat162* __restrict__ outGh, __nv_bfloat162* __restrict__ outGl)
{
    constexpr int NG = 512;
    constexpr int AHo=0, ALo=16384, BHo=32768, BLo=49152;
    extern __shared__ char sm[];
    const int tid=threadIdx.x, lid=tid&31, wid=tid>>5;
    const int wm=wid&3, wn=wid>>2;
    const int m0 = blockIdx.x*128;
    const int n0c = blockIdx.y*128;
    const uint32_t sb = smem_u32(sm);

    float acc[2][8][4];
    #pragma unroll
    for (int i=0;i<2;i++)
        #pragma unroll
        for (int j=0;j<8;j++)
            #pragma unroll
            for (int q=0;q<4;q++) acc[i][j][q]=0.0f;

    #pragma unroll
    for (int it = 0; it < 4; it++) {
        int g = tid + it*256;
        int row = g >> 4, gg = g & 15;
        int sbt = gg >> 3, gin = gg & 7;
        uint32_t off = (uint32_t)(row*128 + gin*16);
        off ^= (off >> 3) & 0x70;
        off += (uint32_t)sbt * 8192;
        size_t src = (size_t)row*NG + n0c + gg*8;
        cpa16(sb + BHo + off, Bh_g + src);
        cpa16(sb + BLo + off, Bl_g + src);
    }
    CP_COMMIT();

    #pragma unroll
    for (int it = 0; it < 4; it++) {
        int g = tid + it*256;
        int row = g >> 3, gg = g & 7;
        uint32_t off = (uint32_t)(row*128 + gg*16);
        off ^= (off >> 3) & 0x70;
        const float* zp = Zsrc + (size_t)(m0+row)*64 + gg*8;
        float4 f0 = *(const float4*)zp;
        float4 f1 = *(const float4*)(zp+4);
        float fv[8] = {f0.x,f0.y,f0.z,f0.w,f1.x,f1.y,f1.z,f1.w};
        alignas(16) __nv_bfloat16 hv[8], lv[8];
        #pragma unroll
        for (int j=0;j<8;j++){
            __nv_bfloat16 h = __float2bfloat16(fv[j]);
            hv[j]=h; lv[j]=__float2bfloat16(fv[j]-__bfloat162float(h));
        }
        *(uint4*)(sm + AHo + off) = *(const uint4*)hv;
        *(uint4*)(sm + ALo + off) = *(const uint4*)lv;
    }
    CP_WAIT(0);
    __syncthreads();

    mma_block<4>(acc, sb+AHo, sb+ALo, sb+BHo, sb+BLo, wm, wn*64, lid);

    const bool isg = (n0c >= 256);
    __nv_bfloat162* oh = isg ? outGh : outDh;
    __nv_bfloat162* ol = isg ? outGl : outDl;
    const int nsub = isg ? 256 : 0;
    const float tval = __ldg(&ts[kstep]);

    #pragma unroll
    for (int nt = 0; nt < 8; nt++) {
        const int n = n0c + wn*64 + nt*8 + (lid&3)*2;
        float2 bb = *(const float2*)(bias512 + n);
        float2 w0 = *(const float2*)(w0512 + n);
        float b0 = fmaf(tval, w0.x, bb.x);
        float b1 = fmaf(tval, w0.y, bb.y);
        #pragma unroll
        for (int mt = 0; mt < 2; mt++) {
            #pragma unroll
            for (int half = 0; half < 2; half++) {
                const int m = m0 + wm*32 + mt*16 + (lid>>2) + half*8;
                float v0 = f_swish(acc[mt][nt][half*2+0] + b0);
                float v1 = f_swish(acc[mt][nt][half*2+1] + b1);
                __nv_bfloat16 h0 = __float2bfloat16(v0);
                __nv_bfloat16 h1 = __float2bfloat16(v1);
                __nv_bfloat16 l0 = __float2bfloat16(v0 - __bfloat162float(h0));
                __nv_bfloat16 l1 = __float2bfloat16(v1 - __bfloat162float(h1));
                size_t pidx = ((size_t)m*256 + (n - nsub)) >> 1;
                __nv_bfloat162 hp; hp.x = h0; hp.y = h1;
                __nv_bfloat162 lp; lp.x = l0; lp.y = l1;
                oh[pidx] = hp;
                ol[pidx] = lp;
            }
        }
    }
}

// ---------------------------------------------------------------------------
// SCAN step kernel (512 threads): d2 -> (d3+g2 merged) -> Euler -> h1(k+1).
// smem: phase1 stages [0,196608); h2 split [0,131072);
//       G stages [131072,196608) 2x32KB; weights Wd3+Wg2 [196608,229376) fixed;
//       P5: z split [0,32768), Wdg hi [32768,98304), lo [98304,163840).
// ---------------------------------------------------------------------------
__global__ void __launch_bounds__(512,1) d23g2_k(
    const __nv_bfloat16* __restrict__ Ah_g, const __nv_bfloat16* __restrict__ Al_g,
    const __nv_bfloat16* __restrict__ Wd2h, const __nv_bfloat16* __restrict__ Wd2l,
    const float* __restrict__ bd2,
    const __nv_bfloat16* __restrict__ Gh, const __nv_bfloat16* __restrict__ Gl,
    const __nv_bfloat16* __restrict__ Wd3h, const __nv_bfloat16* __restrict__ Wd3l,
    const float* __restrict__ bd3,
    const __nv_bfloat16* __restrict__ Wg2h, const __nv_bfloat16* __restrict__ Wg2l,
    const float* __restrict__ bg2,
    const float* __restrict__ Zsrc, const float* __restrict__ ts, int kstep,
    const float* __restrict__ noise, float* __restrict__ zout,
    const __nv_bfloat16* __restrict__ wdgh, const __nv_bfloat16* __restrict__ wdgl,
    const float* __restrict__ bdg, const float* __restrict__ w0dg,
    int do_h1,
    __nv_bfloat162* __restrict__ outDh, __nv_bfloat162* __restrict__ outDl,
    __nv_bfloat162* __restrict__ outGh, __nv_bfloat162* __restrict__ outGl)
{
    extern __shared__ char sm[];
    const int tid=threadIdx.x, lid=tid&31, wid=tid>>5;
    const int wm=wid&3, wn=wid>>2;
    const int m0 = blockIdx.x*128;
    const uint32_t sb = smem_u32(sm);

    // fixed weight window: Wd3h@196608, Wd3l@204800, Wg2h@212992, Wg2l@221184
    auto load_w = [&](int c){
        int row = tid>>3, gg = tid&7;
        uint32_t off = (uint32_t)(row*128 + gg*16); off ^= (off>>3)&0x70;
        size_t src = (size_t)(c*64+row)*64 + gg*8;
        cpa16(sb + 196608u + off, Wd3h + src);
        cpa16(sb + 204800u + off, Wd3l + src);
        cpa16(sb + 212992u + off, Wg2h + src);
        cpa16(sb + 221184u + off, Wg2l + src);
        CP_COMMIT();
    };

    // G (h1 diffusion) double-buffered stages @131072 + s*32768 {Gh 0, Gl 16K}
    auto load_G = [&](int c, int s){
        const uint32_t stb = sb + 131072u + (uint32_t)s*32768u;
        const int c64 = c*64;
        #pragma unroll
        for (int it=0; it<2; it++){
            int g = tid + it*512;
            int row = g>>3, gg = g&7;
            uint32_t off = (uint32_t)(row*128 + gg*16); off ^= (off>>3)&0x70;
            size_t src = (size_t)(m0+row)*256 + c64 + gg*8;
            cpa16(stb + 0     + off, Gh + src);
            cpa16(stb + 16384 + off, Gl + src);
        }
        CP_COMMIT();
    };

    auto load_Wdg = [&](){
        #pragma unroll
        for (int it=0; it<8; it++){
            int g = tid + it*512;
            int row = g>>6, gg = g&63;
            int sbt = gg>>3, gin = gg&7;
            uint32_t off = (uint32_t)(row*128 + gin*16); off ^= (off>>3)&0x70;
            off += (uint32_t)sbt*8192;
            size_t src = (size_t)row*512 + gg*8;
            cpa16(sb + 32768 + off, wdgh + src);
            cpa16(sb + 98304 + off, wdgl + src);
        }
        CP_COMMIT();
    };

    // ======== phase 1: d2 ========
    {
        constexpr int SST = 98304;
        constexpr int AHo=0, ALo=16384, BHo=32768, BLo=65536;

        float acc[2][8][4];
        #pragma unroll
        for (int j=0;j<8;j++)
            #pragma unroll
            for (int q=0;q<4;q++){ acc[0][j][q]=0.0f; acc[1][j][q]=0.0f; }

        auto load_chunk = [&](int c, int s){
            const uint32_t stb = sb + (uint32_t)s*SST;
            const int c64 = c*64;
            #pragma unroll
            for (int it=0; it<2; it++){
                int g = tid + it*512;
                int row = g>>3, gg = g&7;
                uint32_t off = (uint32_t)(row*128 + gg*16); off ^= (off>>3)&0x70;
                size_t src = (size_t)(m0+row)*256 + c64 + gg*8;
                cpa16(stb + AHo + off, Ah_g + src);
                cpa16(stb + ALo + off, Al_g + src);
            }
            #pragma unroll
            for (int it=0; it<4; it++){
                int g = tid + it*512;
                int row = g>>5, gg = g&31;
                int sbt = gg>>3, gin = gg&7;
                uint32_t off = (uint32_t)(row*128 + gin*16); off ^= (off>>3)&0x70;
                off += (uint32_t)sbt*8192;
                size_t src = (size_t)(c64+row)*256 + gg*8;
                cpa16(stb + BHo + off, Wd2h + src);
                cpa16(stb + BLo + off, Wd2l + src);
            }
            CP_COMMIT();
        };

        load_chunk(0, 0);
        load_w(0);                                   // weights chunk 0 into fixed window
        for (int c = 0; c < 4; c++) {
            if (c+1 < 4) { load_chunk(c+1, (c+1)&1); CP_WAIT(1); }
            else         { CP_WAIT(0); }
            __syncthreads();
            const uint32_t stb = sb + (uint32_t)(c&1)*SST;
            mma_block<4>(acc, stb+AHo, stb+ALo, stb+BHo, stb+BLo, wm, wn*64, lid);
            __syncthreads();
        }

        load_G(0, 0);                                // overlap G(0) with h2 epilogue

        #pragma unroll
        for (int nt = 0; nt < 8; nt++) {
            const int n = wn*64 + nt*8 + (lid&3)*2;
            float2 bb = *(const float2*)(bd2 + n);
            const int ck = n >> 6;
            #pragma unroll
            for (int mt = 0; mt < 2; mt++) {
                #pragma unroll
                for (int half = 0; half < 2; half++) {
                    const int r = wm*32 + mt*16 + (lid>>2) + half*8;
                    float v0 = f_swish(acc[mt][nt][half*2+0] + bb.x);
                    float v1 = f_swish(acc[mt][nt][half*2+1] + bb.y);
                    __nv_bfloat16 h0 = __float2bfloat16(v0);
                    __nv_bfloat16 h1 = __float2bfloat16(v1);
                    __nv_bfloat16 l0 = __float2bfloat16(v0 - __bfloat162float(h0));
                    __nv_bfloat16 l1 = __float2bfloat16(v1 - __bfloat162float(h1));
                    uint32_t off = (uint32_t)(r*128 + (n&63)*2); off ^= (off>>3)&0x70;
                    __nv_bfloat162 hp; hp.x=h0; hp.y=h1;
                    __nv_bfloat162 lp; lp.x=l0; lp.y=l1;
                    *(__nv_bfloat162*)(sm + ck*16384 + off) = hp;
                    *(__nv_bfloat162*)(sm + 65536 + ck*16384 + off) = lp;
                }
            }
        }
        __syncthreads();
    }

    // ======== phase 2: d3 + g2 merged (4 chunks) ========
    float accD[2][2][4], accG[2][2][4];
    #pragma unroll
    for (int j=0;j<2;j++)
        #pragma unroll
        for (int q=0;q<4;q++){ accD[0][j][q]=0.0f; accD[1][j][q]=0.0f;
                               accG[0][j][q]=0.0f; accG[1][j][q]=0.0f; }
    for (int c = 0; c < 4; c++) {
        if (c+1 < 4) { load_G(c+1, (c+1)&1); CP_WAIT(1); }
        else         { CP_WAIT(0); }
        __syncthreads();
        // d3: A = h2 chunk c (resident), B = Wd3 chunk c (fixed window)
        mma_block<1>(accD, sb + (uint32_t)c*16384u, sb + 65536u + (uint32_t)c*16384u,
                     sb + 196608u, sb + 204800u, wm, wn*16, lid);
        // g2: A = G stage c&1, B = Wg2 chunk c (fixed window)
        {
            const uint32_t gstb = sb + 131072u + (uint32_t)(c&1)*32768u;
            mma_block<1>(accG, gstb, gstb + 16384u,
                         sb + 212992u, sb + 221184u, wm, wn*16, lid);
        }
        __syncthreads();
        if (c+1 < 4) load_w(c+1);   // refill fixed weight window (post-sync safe)
    }
    if (do_h1) load_Wdg();

    // ======== phase 3: Euler-Maruyama update (+ z_new split to smem) ========
    const float t0 = __ldg(&ts[kstep]);
    const float t1 = __ldg(&ts[kstep+1]);
    const float dt = t1 - t0;
    const float sq = sqrtf(dt);
    const float* noise_k = noise + (size_t)kstep*ZSLICE;

    #pragma unroll
    for (int nt = 0; nt < 2; nt++) {
        const int n = wn*16 + nt*8 + (lid&3)*2;
        float2 bd = *(const float2*)(bd3 + n);
        float2 bg = *(const float2*)(bg2 + n);
        #pragma unroll
        for (int mt = 0; mt < 2; mt++) {
            #pragma unroll
            for (int half = 0; half < 2; half++) {
                const int r = wm*32 + mt*16 + (lid>>2) + half*8;
                const int m = m0 + r;
                float d0 = accD[mt][nt][half*2+0] + bd.x;
                float d1 = accD[mt][nt][half*2+1] + bd.y;
                float g0 = f_softplus(accG[mt][nt][half*2+0] + bg.x);
                float g1 = f_softplus(accG[mt][nt][half*2+1] + bg.y);
                size_t idx = (size_t)m*64 + n;
                float2 zz = *(const float2*)(Zsrc + idx);
                float2 nn = *(const float2*)(noise_k + idx);
                float z0 = zz.x + d0*dt + g0*sq*nn.x;
                float z1 = zz.y + d1*dt + g1*sq*nn.y;
                *(float2*)(zout + idx) = make_float2(z0, z1);
                if (do_h1) {
                    __nv_bfloat16 h0 = __float2bfloat16(z0);
                    __nv_bfloat16 h1 = __float2bfloat16(z1);
                    __nv_bfloat16 l0 = __float2bfloat16(z0 - __bfloat162float(h0));
                    __nv_bfloat16 l1 = __float2bfloat16(z1 - __bfloat162float(h1));
                    uint32_t off = (uint32_t)(r*128 + n*2); off ^= (off>>3)&0x70;
                    __nv_bfloat162 hp; hp.x=h0; hp.y=h1;
                    __nv_bfloat162 lp; lp.x=l0; lp.y=l1;
                    *(__nv_bfloat162*)(sm + off) = hp;
                    *(__nv_bfloat162*)(sm + 16384 + off) = lp;
                }
            }
        }
    }

    // ======== phase 4: h1(k+1) = swish([t1, z_new] @ [Wd1|Wg1]) ========
    if (do_h1) {
        CP_WAIT(0);
        __syncthreads();
        #pragma unroll
        for (int hb = 0; hb < 2; hb++) {
            float acc5[2][8][4];
            #pragma unroll
            for (int j=0;j<8;j++)
                #pragma unroll
                for (int q=0;q<4;q++){ acc5[0][j][q]=0.0f; acc5[1][j][q]=0.0f; }

            mma_block<4>(acc5, sb, sb+16384u,
                         sb+32768u + (uint32_t)hb*32768u,
                         sb+98304u + (uint32_t)hb*32768u, wm, wn*64, lid);

            __nv_bfloat162* oh = hb ? outGh : outDh;
            __nv_bfloat162* ol = hb ? outGl : outDl;
            #pragma unroll
            for (int nt = 0; nt < 8; nt++) {
                const int nl = wn*64 + nt*8 + (lid&3)*2;
                const int ng = hb*256 + nl;
                float2 bb = *(const float2*)(bdg + ng);
                float2 w0 = *(const float2*)(w0dg + ng);
                float b0 = fmaf(t1, w0.x, bb.x);
                float b1 = fmaf(t1, w0.y, bb.y);
                #pragma unroll
                for (int mt = 0; mt < 2; mt++) {
                    #pragma unroll
                    for (int half = 0; half < 2; half++) {
                        const int m = m0 + wm*32 + mt*16 + (lid>>2) + half*8;
                        float v0 = f_swish(acc5[mt][nt][half*2+0] + b0);
                        float v1 = f_swish(acc5[mt][nt][half*2+1] + b1);
                        __nv_bfloat16 h0 = __float2bfloat16(v0);
                        __nv_bfloat16 h1 = __float2bfloat16(v1);
                        __nv_bfloat16 l0 = __float2bfloat16(v0 - __bfloat162float(h0));
                        __nv_bfloat16 l1 = __float2bfloat16(v1 - __bfloat162float(h1));
                        size_t pidx = ((size_t)m*256 + nl) >> 1;
                        __nv_bfloat162 hp; hp.x=h0; hp.y=h1;
                        __nv_bfloat162 lp; lp.x=l0; lp.y=l1;
                        oh[pidx] = hp;
                        ol[pidx] = lp;
                    }
                }
            }
        }
    }
}

// ---------------- prep: ALL elementwise splits in ONE kernel ----------------
#define PREP_TOTAL (4194304 + 671744)
__global__ void prep_all(
    const float* __restrict__ x,
    const float* __restrict__ W_in, const float* __restrict__ Wb1,
    const float* __restrict__ Wb2,  const float* __restrict__ W_fo,
    const float* __restrict__ W_lat,const float* __restrict__ W_init,
    const float* __restrict__ Wd2,  const float* __restrict__ Wd3,
    const float* __restrict__ Wg2,
    __nv_bfloat16* __restrict__ xh, __nv_bfloat16* __restrict__ xl,
    __nv_bfloat16* __restrict__ wh, __nv_bfloat16* __restrict__ wl)
{
    int i = blockIdx.x * 256 + threadIdx.x;
    float v;
    __nv_bfloat16 *dh, *dl;
    if (i < 4194304) {
        v = x[i]; dh = xh + i; dl = xl + i;
    } else {
        int j = i - 4194304;
        const float* s; int base;
        if      (j < 65536)            { s = W_in;   base = OFF_WIN;   }
        else if ((j -= 65536) < 196608){ s = Wb1;    base = OFF_WB1;   }
        else if ((j -= 196608) < 196608){ s = Wb2;   base = OFF_WB2;   }
        else if ((j -= 196608) < 65536){ s = W_fo;   base = OFF_WFO;   }
        else if ((j -= 65536) < 32768) { s = W_lat;  base = OFF_WLAT;  }
        else if ((j -= 32768) < 16384) { s = W_init; base = OFF_WINIT; }
        else if ((j -= 16384) < 65536) { s = Wd2;    base = OFF_WD2;   }
        else if ((j -= 65536) < 16384) { s = Wd3;    base = OFF_WD3;   }
        else                           { j -= 16384; s = Wg2; base = OFF_WG2; }
        v = s[j]; dh = wh + base + j; dl = wl + base + j;
    }
    __nv_bfloat16 h = __float2bfloat16(v);
    *dh = h;
    *dl = __float2bfloat16(v - __bfloat162float(h));
}

__global__ void prep_dg1(const float* __restrict__ Wd1, const float* __restrict__ Wg1,
                         const float* __restrict__ bd1, const float* __restrict__ bg1,
                         __nv_bfloat16* __restrict__ wh, __nv_bfloat16* __restrict__ wl,
                         float* __restrict__ bias, float* __restrict__ w0)
{
    int idx = blockIdx.x * 256 + threadIdx.x;   // 64*512
    int k = idx >> 9, n = idx & 511;
    float v = (n < 256) ? Wd1[(size_t)(k+1)*256 + n] : Wg1[(size_t)(k+1)*256 + (n-256)];
    __nv_bfloat16 h = __float2bfloat16(v);
    wh[idx] = h;
    wl[idx] = __float2bfloat16(v - __bfloat162float(h));
    if (idx < 512) {
        bias[idx] = (idx < 256) ? bd1[idx] : bg1[idx-256];
        w0[idx]   = (idx < 256) ? Wd1[idx] : Wg1[idx-256];
    }
}

// ---------------------------------------------------------------------------
extern "C" void kernel_launch(void* const* d_in, const int* in_sizes, int n_in,
                              void* d_out, int out_size)
{
    const float* x     = (const float*)d_in[0];
    const float* ts    = (const float*)d_in[1];
    const float* noise = (const float*)d_in[2];
    const float* W_in  = (const float*)d_in[3];
    const float* b_in  = (const float*)d_in[4];
    const float* Wb1   = (const float*)d_in[5];
    const float* bb1   = (const float*)d_in[6];
    const float* Wb2   = (const float*)d_in[7];
    const float* bb2   = (const float*)d_in[8];
    const float* W_fo  = (const float*)d_in[9];
    const float* b_fo  = (const float*)d_in[10];
    const float* W_lat = (const float*)d_in[11];
    const float* b_lat = (const float*)d_in[12];
    const float* W_init= (const float*)d_in[13];
    const float* b_init= (const float*)d_in[14];
    const float* Wd1   = (const float*)d_in[15];
    const float* bd1   = (const float*)d_in[16];
    const float* Wd2   = (const float*)d_in[17];
    const float* bd2   = (const float*)d_in[18];
    const float* Wd3   = (const float*)d_in[19];
    const float* bd3   = (const float*)d_in[20];
    const float* Wg1   = (const float*)d_in[21];
    const float* bg1   = (const float*)d_in[22];
    const float* Wg2   = (const float*)d_in[23];
    const float* bg2   = (const float*)d_in[24];
    float* out = (float*)d_out;

    __nv_bfloat16 *xh, *xl, *ah, *al, *bh, *bl, *gh, *gl, *wh, *wl, *wdgh, *wdgl;
    float *hres, *bdg, *w0dg;
    cudaGetSymbolAddress((void**)&xh,  g_xh);
    cudaGetSymbolAddress((void**)&xl,  g_xl);
    cudaGetSymbolAddress((void**)&ah,  g_ah);
    cudaGetSymbolAddress((void**)&al,  g_al);
    cudaGetSymbolAddress((void**)&bh,  g_bh);
    cudaGetSymbolAddress((void**)&bl,  g_bl);
    cudaGetSymbolAddress((void**)&gh,  g_gh);
    cudaGetSymbolAddress((void**)&gl,  g_gl);
    cudaGetSymbolAddress((void**)&wh,  g_wh);
    cudaGetSymbolAddress((void**)&wl,  g_wl);
    cudaGetSymbolAddress((void**)&wdgh,g_wdgh);
    cudaGetSymbolAddress((void**)&wdgl,g_wdgl);
    cudaGetSymbolAddress((void**)&hres,g_hres);
    cudaGetSymbolAddress((void**)&bdg, g_bdg);
    cudaGetSymbolAddress((void**)&w0dg,g_w0dg);

    // ---- prep: 2 launches total ----
    prep_all<<<PREP_TOTAL/256, 256>>>(x, W_in, Wb1, Wb2, W_fo, W_lat, W_init,
                                      Wd2, Wd3, Wg2, xh, xl, wh, wl);
    prep_dg1<<<128, 256>>>(Wd1, Wg1, bd1, bg1, wdgh, wdgl, bdg, w0dg);

    // ---- encoder kernel handles ----
    auto* kIN  = mgemm<256,256,ACT_SWISH, false,true, true >;
    auto* kFO  = mgemm<256,256,ACT_NONE,  false,true, false>;

    const int SM128 = 32768 + 2*128*128;   // 65536
    const int SM64  = 32768 + 2*64*128;    // 49152
    cudaFuncSetAttribute((const void*)kIN,  cudaFuncAttributeMaxDynamicSharedMemorySize, SM128);
    cudaFuncSetAttribute((const void*)kFO,  cudaFuncAttributeMaxDynamicSharedMemorySize, SM128);
    cudaFuncSetAttribute((const void*)blk_k,   cudaFuncAttributeMaxDynamicSharedMemorySize, 196608);
    cudaFuncSetAttribute((const void*)tail_k,  cudaFuncAttributeMaxDynamicSharedMemorySize, SM64);
    cudaFuncSetAttribute((const void*)dg1_k,   cudaFuncAttributeMaxDynamicSharedMemorySize, 65536);
    cudaFuncSetAttribute((const void*)d23g2_k, cudaFuncAttributeMaxDynamicSharedMemorySize, 229376);

    dim3 blk(256);
    dim3 gN256(BATCH/128, 2);

    __nv_bfloat162 *ah2 = (__nv_bfloat162*)ah, *al2 = (__nv_bfloat162*)al;
    __nv_bfloat162 *bh2 = (__nv_bfloat162*)bh, *bl2 = (__nv_bfloat162*)bl;
    __nv_bfloat162 *gh2 = (__nv_bfloat162*)gh, *gl2 = (__nv_bfloat162*)gl;

    // ---- encoder ----
    kIN<<<gN256, blk, SM128>>>(xh, xl, wh+OFF_WIN, wl+OFF_WIN, b_in,
                               nullptr, hres, ah2, al2);
    for (int i = 0; i < 3; i++) {
        blk_k<<<dim3(BATCH/128), dim3(512), 196608>>>(
            ah, al,
            wh+OFF_WB1+i*65536, wl+OFF_WB1+i*65536, bb1 + i*HID,
            wh+OFF_WB2+i*65536, wl+OFF_WB2+i*65536, bb2 + i*HID,
            hres, ah2, al2);
    }
    kFO<<<gN256, blk, SM128>>>(ah, al, wh+OFF_WFO, wl+OFF_WFO, b_fo,
                               nullptr, nullptr, bh2, bl2);
    tail_k<<<dim3(BATCH/128, 3), blk, SM64>>>(bh, bl,
                                              wh+OFF_WLAT, wl+OFF_WLAT, b_lat,
                                              wh+OFF_WINIT, wl+OFF_WINIT, b_init,
                                              out);

    // ---- SDE scan: dg1 once for z0, then 1 kernel/step ----
    dg1_k<<<dim3(BATCH/128, 4), blk, 65536>>>(out + OUT_Z_OFF, wdgh, wdgl, bdg, w0dg,
                                              ts, 0, ah2, al2, gh2, gl2);
    for (int k = 0; k < NSTEP; k++) {
        const float* z = out + OUT_Z_OFF + (size_t)k * ZSLICE;
        float* zn = out + OUT_Z_OFF + (size_t)(k+1) * ZSLICE;
        d23g2_k<<<dim3(BATCH/128, 1), dim3(512), 229376>>>(
            ah, al, wh+OFF_WD2, wl+OFF_WD2, bd2,
            gh, gl, wh+OFF_WD3, wl+OFF_WD3, bd3,
            wh+OFF_WG2, wl+OFF_WG2, bg2,
            z, ts, k, noise, zn,
            wdgh, wdgl, bdg, w0dg, (k+1 < NSTEP) ? 1 : 0,
            ah2, al2, gh2, gl2);
    }
}